// round 7
// baseline (speedup 1.0000x reference)
#include <cuda_runtime.h>
#include <cuda_bf16.h>
#include <cstdint>

#define BATCHN 4096
#define SEQLEN 80
#define EMBD   100
#define UNITS  64
#define NG     256                 // 4*UNITS gates
#define MTOT   (BATCHN * SEQLEN)

// ---------------- device scratch (allocation-free: device globals) ----------
__device__ __nv_bfloat16 g_h1bf [(size_t)MTOT * UNITS];  // 42 MB layer-1 hidden seq (bf16)
__device__ float         g_h2   [BATCHN * UNITS];        //  1 MB layer-2 last hidden
__device__ __nv_bfloat16 g_embbf[10000 * 128];           // 2.5 MB emb->bf16, K padded to 128
__device__ __nv_bfloat16 g_Wt1  [256 * 128];             // W1^T bf16 [n][k], k padded to 128
__device__ __nv_bfloat16 g_Wt2  [256 * 64];              // W2^T bf16 [n][k], k=64

// ---------------- helpers ---------------------------------------------------
__device__ __forceinline__ float tanhapx(float x) {
    float y; asm("tanh.approx.f32 %0, %1;" : "=f"(y) : "f"(x)); return y;
}
__device__ __forceinline__ float sigf(float x) { return fmaf(0.5f, tanhapx(0.5f * x), 0.5f); }

__device__ __forceinline__ uint32_t smem_u32(const void* p) {
    uint32_t a;
    asm("{ .reg .u64 t; cvta.to.shared.u64 t, %1; cvt.u32.u64 %0, t; }" : "=r"(a) : "l"(p));
    return a;
}
__device__ __forceinline__ uint32_t packbf(float x, float y) {
    __nv_bfloat162 v = __float22bfloat162_rn(make_float2(x, y));
    return *(uint32_t*)&v;
}
__device__ __forceinline__ void mma16816(float* d, const uint32_t* a, const uint32_t* b) {
    asm volatile(
        "mma.sync.aligned.m16n8k16.row.col.f32.bf16.bf16.f32 "
        "{%0,%1,%2,%3}, {%4,%5,%6,%7}, {%8,%9}, {%0,%1,%2,%3};"
        : "+f"(d[0]), "+f"(d[1]), "+f"(d[2]), "+f"(d[3])
        : "r"(a[0]), "r"(a[1]), "r"(a[2]), "r"(a[3]), "r"(b[0]), "r"(b[1]));
}
__device__ __forceinline__ void ldmx4(uint32_t* r, uint32_t addr) {
    asm volatile("ldmatrix.sync.aligned.m8n8.x4.shared.b16 {%0,%1,%2,%3}, [%4];"
        : "=r"(r[0]), "=r"(r[1]), "=r"(r[2]), "=r"(r[3]) : "r"(addr));
}
__device__ __forceinline__ void cpa16(uint32_t dst, const void* gsrc) {
    asm volatile("{ .reg .u64 ga; cvta.to.global.u64 ga, %1; "
                 "cp.async.ca.shared.global [%0], [ga], 16; }"
                 :: "r"(dst), "l"(gsrc) : "memory");
}
#define CPA_COMMIT() asm volatile("cp.async.commit_group;" ::: "memory")
#define CPA_WAIT0()  asm volatile("cp.async.wait_group 0;" ::: "memory")

// ---------------------------------------------------------------------------
// Pre-conversion kernels
// ---------------------------------------------------------------------------
__global__ void conv_emb_kernel(const float* __restrict__ emb) {
    int idx = blockIdx.x * 256 + threadIdx.x;           // over 10000*128
    int v = idx >> 7, c = idx & 127;
    g_embbf[idx] = (c < EMBD) ? __float2bfloat16(emb[v * EMBD + c]) : __nv_bfloat16(0.f);
}
__global__ void conv_w1_kernel(const float* __restrict__ W) {
    int idx = blockIdx.x * 256 + threadIdx.x;           // over 256*128
    int n = idx >> 7, c = idx & 127;
    g_Wt1[idx] = (c < EMBD) ? __float2bfloat16(W[c * NG + n]) : __nv_bfloat16(0.f);
}
__global__ void conv_w2_kernel(const float* __restrict__ W) {
    int idx = blockIdx.x * 256 + threadIdx.x;           // over 256*64
    int n = idx >> 6, c = idx & 63;
    g_Wt2[idx] = __float2bfloat16(W[c * NG + n]);
}

// ---------------------------------------------------------------------------
// Fused LSTM layer with software-pipelined x-projection:
//  - accX(t+1) = bias + x(t+1)@W is computed DURING step t (independent of
//    the recurrence) -> step-t critical path is only h@U (4-chained mma) +
//    gate MUFU tree. x tiles staged via cp.async two steps ahead.
//  - W, U in registers as B fragments; h double-buffered in SMEM; c in regs.
// ---------------------------------------------------------------------------
template<int KX, int LAYER>
__global__ void __launch_bounds__(256, 1) lstm_fused(
    const int*   __restrict__ tokens,
    const float* __restrict__ U,
    const float* __restrict__ bias)
{
    constexpr int KXP = KX + 8;            // x row stride (bf16): 120 / 72
    constexpr int NKT = KX / 16;           // x k-tiles: 7 / 4
    constexpr int NCH = KX / 8;            // 16B chunks per x row: 14 / 8

    __shared__ __nv_bfloat16 xs[2][32][KXP];
    __shared__ __nv_bfloat16 hsm[2][32][72];
    __shared__ int toks[(LAYER == 1) ? 32 * SEQLEN : 8];

    const int tid = threadIdx.x, wid = tid >> 5, lid = tid & 31;
    const int g = lid >> 2, t4 = lid & 3;
    const int b0 = blockIdx.x * 32;

    {   // zero h buffers
        uint32_t* hz = (uint32_t*)&hsm[0][0][0];
        for (int i = tid; i < 2 * 32 * 72 / 2; i += 256) hz[i] = 0u;
    }
    if (LAYER == 1) {
        for (int idx = tid; idx < 32 * SEQLEN; idx += 256)
            toks[idx] = tokens[(size_t)(b0 + idx / SEQLEN) * SEQLEN + idx % SEQLEN];
    }

    // ---- B fragments: W (bf16 pre-transposed) and U (packed from f32) ----
    const __nv_bfloat16* Wt = (LAYER == 1) ? g_Wt1 : g_Wt2;
    constexpr int WSTR = (LAYER == 1) ? 128 : 64;
    uint32_t bw[4][NKT][2], bu[4][4][2];
    float bx[4][2];
    #pragma unroll
    for (int gg = 0; gg < 4; gg++) {
        const int n = gg * 64 + wid * 8 + g;
        #pragma unroll
        for (int kt = 0; kt < NKT; kt++) {
            const __nv_bfloat16* wb = Wt + (size_t)n * WSTR + kt * 16 + t4 * 2;
            bw[gg][kt][0] = *(const uint32_t*)wb;
            bw[gg][kt][1] = *(const uint32_t*)(wb + 8);
        }
        #pragma unroll
        for (int kt = 0; kt < 4; kt++) {
            const int k0 = kt * 16 + t4 * 2;
            bu[gg][kt][0] = packbf(U[(size_t)k0 * NG + n],       U[(size_t)(k0 + 1) * NG + n]);
            bu[gg][kt][1] = packbf(U[(size_t)(k0 + 8) * NG + n], U[(size_t)(k0 + 9) * NG + n]);
        }
        const int col = gg * 64 + wid * 8 + t4 * 2;
        bx[gg][0] = bias[col]; bx[gg][1] = bias[col + 1];
    }
    __syncthreads();   // toks + zeroed h visible

    const uint32_t xs0 = smem_u32(&xs[0][0][0]);
    const uint32_t xs1 = smem_u32(&xs[1][0][0]);
    const uint32_t h0b = smem_u32(&hsm[0][0][0]);
    const uint32_t h1b = smem_u32(&hsm[1][0][0]);
    const uint32_t a_lane_x = (uint32_t)((lid & 15) * (KXP * 2) + (lid >> 4) * 16);
    const uint32_t a_lane_h = (uint32_t)((lid & 15) * 144 + (lid >> 4) * 16);

    auto stage_x = [&](int buf, int t) {
        const uint32_t dbase = buf ? xs1 : xs0;
        if (LAYER == 1) {
            for (int idx = tid; idx < 32 * NCH; idx += 256) {
                int row = idx / NCH, ch = idx - row * NCH;
                int tok = toks[row * SEQLEN + t];
                cpa16(dbase + row * (KXP * 2) + ch * 16,
                      g_embbf + (size_t)tok * 128 + ch * 8);
            }
        } else {
            for (int idx = tid; idx < 32 * NCH; idx += 256) {
                int row = idx >> 3, ch = idx & 7;
                cpa16(dbase + row * (KXP * 2) + ch * 16,
                      g_h1bf + ((size_t)(b0 + row) * SEQLEN + t) * UNITS + ch * 8);
            }
        }
    };
    auto xproj = [&](float accX[2][4][4], uint32_t xb) {
        #pragma unroll
        for (int mt = 0; mt < 2; mt++)
            #pragma unroll
            for (int gg = 0; gg < 4; gg++) {
                accX[mt][gg][0] = bx[gg][0]; accX[mt][gg][1] = bx[gg][1];
                accX[mt][gg][2] = bx[gg][0]; accX[mt][gg][3] = bx[gg][1];
            }
        #pragma unroll
        for (int kt = 0; kt < NKT; kt++) {
            uint32_t a0[4], a1[4];
            ldmx4(a0, xb + a_lane_x + (uint32_t)(kt * 32));
            ldmx4(a1, xb + a_lane_x + (uint32_t)(16 * KXP * 2 + kt * 32));
            #pragma unroll
            for (int gg = 0; gg < 4; gg++) {
                mma16816(accX[0][gg], a0, bw[gg][kt]);
                mma16816(accX[1][gg], a1, bw[gg][kt]);
            }
        }
    };

    // prologue: stage x(0), x(1); accX = bias + x(0)@W
    stage_x(0, 0);
    stage_x(1, 1);
    CPA_COMMIT();
    CPA_WAIT0();
    __syncthreads();

    float accX[2][4][4];
    xproj(accX, xs0);
    __syncthreads();   // all warps done reading xs[0] before t=0 stages x(2) into it

    float cst[2][2][2];
    #pragma unroll
    for (int mt = 0; mt < 2; mt++)
        for (int rs = 0; rs < 2; rs++)
            for (int uu = 0; uu < 2; uu++) cst[mt][rs][uu] = 0.f;

    int p = 0;
    for (int t = 0; t < SEQLEN; ++t) {
        // acc(t) = bias + x(t)@W (pipelined in) ; add h(t-1)@U
        float acc[2][4][4];
        #pragma unroll
        for (int mt = 0; mt < 2; mt++)
            #pragma unroll
            for (int gg = 0; gg < 4; gg++)
                #pragma unroll
                for (int r = 0; r < 4; r++) acc[mt][gg][r] = accX[mt][gg][r];

        const uint32_t hb = p ? h1b : h0b;
        #pragma unroll
        for (int kt = 0; kt < 4; kt++) {
            uint32_t a0[4], a1[4];
            ldmx4(a0, hb + a_lane_h + (uint32_t)(kt * 32));
            ldmx4(a1, hb + a_lane_h + (uint32_t)(16 * 144 + kt * 32));
            #pragma unroll
            for (int gg = 0; gg < 4; gg++) {
                mma16816(acc[0][gg], a0, bu[gg][kt]);
                mma16816(acc[1][gg], a1, bu[gg][kt]);
            }
        }

        // independent work for t+1: x@W into accX, stage x(t+2)
        if (t + 1 < SEQLEN) {
            xproj(accX, ((t + 1) & 1) ? xs1 : xs0);
            if (t + 2 < SEQLEN) stage_x(t & 1, t + 2);
            CPA_COMMIT();
        }

        // gates + state update + h write
        #pragma unroll
        for (int mt = 0; mt < 2; mt++)
            #pragma unroll
            for (int rs = 0; rs < 2; rs++) {
                const int row = mt * 16 + g + rs * 8;
                float hv0, hv1;
                {
                    float zi = acc[mt][0][rs * 2], zf = acc[mt][1][rs * 2];
                    float zg = acc[mt][2][rs * 2], zo = acc[mt][3][rs * 2];
                    float cn = sigf(zf) * cst[mt][rs][0] + sigf(zi) * tanhapx(zg);
                    cst[mt][rs][0] = cn;
                    hv0 = sigf(zo) * tanhapx(cn);
                }
                {
                    float zi = acc[mt][0][rs * 2 + 1], zf = acc[mt][1][rs * 2 + 1];
                    float zg = acc[mt][2][rs * 2 + 1], zo = acc[mt][3][rs * 2 + 1];
                    float cn = sigf(zf) * cst[mt][rs][1] + sigf(zi) * tanhapx(zg);
                    cst[mt][rs][1] = cn;
                    hv1 = sigf(zo) * tanhapx(cn);
                }
                __nv_bfloat162 h2 = __float22bfloat162_rn(make_float2(hv0, hv1));
                *(__nv_bfloat162*)&hsm[p ^ 1][row][wid * 8 + t4 * 2] = h2;
                if (LAYER == 1) {
                    *(__nv_bfloat162*)&g_h1bf[((size_t)(b0 + row) * SEQLEN + t) * UNITS +
                                              wid * 8 + t4 * 2] = h2;
                } else if (t == SEQLEN - 1) {
                    *(float2*)&g_h2[(size_t)(b0 + row) * UNITS + wid * 8 + t4 * 2] =
                        make_float2(hv0, hv1);
                }
            }

        CPA_WAIT0();      // x(t+2) landed
        __syncthreads();  // h(t) + x buffers consistent across warps
        p ^= 1;
    }
}

// ---------------------------------------------------------------------------
// Final dense + sigmoid
// ---------------------------------------------------------------------------
__global__ void __launch_bounds__(128) dense_kernel(
    const float* __restrict__ Wd, const float* __restrict__ bd,
    float* __restrict__ out)
{
    __shared__ float wds[64];
    if (threadIdx.x < 64) wds[threadIdx.x] = Wd[threadIdx.x];
    __syncthreads();
    int b = blockIdx.x * blockDim.x + threadIdx.x;
    float s = bd[0];
    const float* h = &g_h2[b * 64];
    #pragma unroll
    for (int u = 0; u < 64; u++) s += h[u] * wds[u];
    out[b] = 1.0f / (1.0f + __expf(-s));
}

// ---------------------------------------------------------------------------
extern "C" void kernel_launch(void* const* d_in, const int* in_sizes, int n_in,
                              void* d_out, int out_size)
{
    const int*   tokens = (const int*)  d_in[0];
    const float* emb    = (const float*)d_in[1];
    const float* W1     = (const float*)d_in[2];
    const float* U1     = (const float*)d_in[3];
    const float* b1     = (const float*)d_in[4];
    const float* W2     = (const float*)d_in[5];
    const float* U2     = (const float*)d_in[6];
    const float* b2     = (const float*)d_in[7];
    const float* Wd     = (const float*)d_in[8];
    const float* bd     = (const float*)d_in[9];
    float* out = (float*)d_out;

    // one-time bf16 conversions (zero-padded where needed)
    conv_emb_kernel<<<10000 * 128 / 256, 256>>>(emb);
    conv_w1_kernel<<<256 * 128 / 256, 256>>>(W1);
    conv_w2_kernel<<<256 * 64 / 256, 256>>>(W2);

    // layer 1: fused (emb gather + x@W1 + h@U1), emits h1 bf16
    lstm_fused<112, 1><<<BATCHN / 32, 256>>>(tokens, U1, b1);
    // layer 2: fused (h1 stream + x@W2 + h@U2), keeps last h
    lstm_fused<64, 2><<<BATCHN / 32, 256>>>(nullptr, U2, b2);

    // head
    dense_kernel<<<BATCHN / 128, 128>>>(Wd, bd, out);
}

// round 8
// speedup vs baseline: 1.0375x; 1.0375x over previous
#include <cuda_runtime.h>
#include <cuda_bf16.h>
#include <cstdint>

#define BATCHN 4096
#define SEQLEN 80
#define EMBD   100
#define UNITS  64
#define NG     256                 // 4*UNITS gates

// ---------------- device scratch (allocation-free: device globals) ----------
__device__ __nv_bfloat16 g_embbf[10000 * 128];           // 2.5 MB emb->bf16, K padded to 128
__device__ __nv_bfloat16 g_Wt1  [256 * 128];             // W1^T bf16 [n][k], k padded to 128
__device__ __nv_bfloat16 g_Wt2  [256 * 64];              // W2^T bf16 [n][k], k=64

// ---------------- helpers ---------------------------------------------------
__device__ __forceinline__ float tanhapx(float x) {
    float y; asm("tanh.approx.f32 %0, %1;" : "=f"(y) : "f"(x)); return y;
}
__device__ __forceinline__ float sigf(float x) { return fmaf(0.5f, tanhapx(0.5f * x), 0.5f); }

__device__ __forceinline__ uint32_t smem_u32(const void* p) {
    uint32_t a;
    asm("{ .reg .u64 t; cvta.to.shared.u64 t, %1; cvt.u32.u64 %0, t; }" : "=r"(a) : "l"(p));
    return a;
}
__device__ __forceinline__ uint32_t packbf(float x, float y) {
    __nv_bfloat162 v = __float22bfloat162_rn(make_float2(x, y));
    return *(uint32_t*)&v;
}
__device__ __forceinline__ void mma16816(float* d, const uint32_t* a, const uint32_t* b) {
    asm volatile(
        "mma.sync.aligned.m16n8k16.row.col.f32.bf16.bf16.f32 "
        "{%0,%1,%2,%3}, {%4,%5,%6,%7}, {%8,%9}, {%0,%1,%2,%3};"
        : "+f"(d[0]), "+f"(d[1]), "+f"(d[2]), "+f"(d[3])
        : "r"(a[0]), "r"(a[1]), "r"(a[2]), "r"(a[3]), "r"(b[0]), "r"(b[1]));
}
__device__ __forceinline__ void ldmx4(uint32_t* r, uint32_t addr) {
    asm volatile("ldmatrix.sync.aligned.m8n8.x4.shared.b16 {%0,%1,%2,%3}, [%4];"
        : "=r"(r[0]), "=r"(r[1]), "=r"(r[2]), "=r"(r[3]) : "r"(addr));
}
__device__ __forceinline__ void cpa16(uint32_t dst, const void* gsrc) {
    asm volatile("{ .reg .u64 ga; cvta.to.global.u64 ga, %1; "
                 "cp.async.ca.shared.global [%0], [ga], 16; }"
                 :: "r"(dst), "l"(gsrc) : "memory");
}
#define CPA_COMMIT() asm volatile("cp.async.commit_group;" ::: "memory")
#define CPA_WAIT0()  asm volatile("cp.async.wait_group 0;" ::: "memory")

// ---------------------------------------------------------------------------
// Pre-conversion kernels
// ---------------------------------------------------------------------------
__global__ void conv_emb_kernel(const float* __restrict__ emb) {
    int idx = blockIdx.x * 256 + threadIdx.x;           // over 10000*128
    int v = idx >> 7, c = idx & 127;
    g_embbf[idx] = (c < EMBD) ? __float2bfloat16(emb[v * EMBD + c]) : __nv_bfloat16(0.f);
}
__global__ void conv_w1_kernel(const float* __restrict__ W) {
    int idx = blockIdx.x * 256 + threadIdx.x;           // over 256*128
    int n = idx >> 7, c = idx & 127;
    g_Wt1[idx] = (c < EMBD) ? __float2bfloat16(W[c * NG + n]) : __nv_bfloat16(0.f);
}
__global__ void conv_w2_kernel(const float* __restrict__ W) {
    int idx = blockIdx.x * 256 + threadIdx.x;           // over 256*64
    int n = idx >> 6, c = idx & 63;
    g_Wt2[idx] = __float2bfloat16(W[c * NG + n]);
}

// ---------------------------------------------------------------------------
// BOTH LSTM layers + dense head in ONE kernel. 128 CTAs x 256 thr, 32 rows.
// Layer 2 lags layer 1 by one step: at outer step t, layer1 computes h1(t)
// from (x(t), h1(t-1)); layer2 computes h2(t-1) from (h1(t-1), h2(t-2)).
// Both read h1sm[p]; writes go to the p^1 buffers; ONE barrier per step.
// h1 never touches DRAM. W1/W2/U1/U2 as register B-fragments; bias in SMEM;
// c states in registers; emb x-tiles staged via cp.async one step ahead.
// After the loop, h2(79) (staged as f32 in SMEM) -> dense + sigmoid -> out.
// ---------------------------------------------------------------------------
__global__ void __launch_bounds__(256, 1) lstm_both(
    const int*   __restrict__ tokens,
    const float* __restrict__ U1,
    const float* __restrict__ b1,
    const float* __restrict__ U2,
    const float* __restrict__ b2,
    const float* __restrict__ Wd,
    const float* __restrict__ bd,
    float*       __restrict__ out)
{
    __shared__ __align__(16) __nv_bfloat16 xs[2][32][120];   // layer1 x tiles (K=112+pad)
    __shared__ __align__(16) __nv_bfloat16 h1sm[2][32][72];
    __shared__ __align__(16) __nv_bfloat16 h2sm[2][32][72];
    __shared__ int   toks[32 * SEQLEN];
    __shared__ float bsm[2][NG];

    const int tid = threadIdx.x, wid = tid >> 5, lid = tid & 31;
    const int g = lid >> 2, t4 = lid & 3;
    const int b0 = blockIdx.x * 32;

    {   // zero h buffers
        uint32_t* z1 = (uint32_t*)&h1sm[0][0][0];
        for (int i = tid; i < 2 * 32 * 72 / 2; i += 256) z1[i] = 0u;
        uint32_t* z2 = (uint32_t*)&h2sm[0][0][0];
        for (int i = tid; i < 2 * 32 * 72 / 2; i += 256) z2[i] = 0u;
    }
    for (int idx = tid; idx < 32 * SEQLEN; idx += 256)
        toks[idx] = tokens[(size_t)(b0 + idx / SEQLEN) * SEQLEN + idx % SEQLEN];
    for (int idx = tid; idx < NG; idx += 256) {
        bsm[0][idx] = b1[idx];
        bsm[1][idx] = b2[idx];
    }

    // ---- register B-fragments: W1 (7 kt), U1, W2, U2 (4 kt each) ----
    uint32_t bw1[4][7][2], bu1[4][4][2], bw2[4][4][2], bu2[4][4][2];
    #pragma unroll
    for (int gg = 0; gg < 4; gg++) {
        const int n = gg * 64 + wid * 8 + g;
        #pragma unroll
        for (int kt = 0; kt < 7; kt++) {
            const __nv_bfloat16* wb = g_Wt1 + (size_t)n * 128 + kt * 16 + t4 * 2;
            bw1[gg][kt][0] = *(const uint32_t*)wb;
            bw1[gg][kt][1] = *(const uint32_t*)(wb + 8);
        }
        #pragma unroll
        for (int kt = 0; kt < 4; kt++) {
            const __nv_bfloat16* wb = g_Wt2 + (size_t)n * 64 + kt * 16 + t4 * 2;
            bw2[gg][kt][0] = *(const uint32_t*)wb;
            bw2[gg][kt][1] = *(const uint32_t*)(wb + 8);
            const int k0 = kt * 16 + t4 * 2;
            bu1[gg][kt][0] = packbf(U1[(size_t)k0 * NG + n],       U1[(size_t)(k0 + 1) * NG + n]);
            bu1[gg][kt][1] = packbf(U1[(size_t)(k0 + 8) * NG + n], U1[(size_t)(k0 + 9) * NG + n]);
            bu2[gg][kt][0] = packbf(U2[(size_t)k0 * NG + n],       U2[(size_t)(k0 + 1) * NG + n]);
            bu2[gg][kt][1] = packbf(U2[(size_t)(k0 + 8) * NG + n], U2[(size_t)(k0 + 9) * NG + n]);
        }
    }
    __syncthreads();   // toks/bias/zeroed h visible

    const uint32_t xs0 = smem_u32(&xs[0][0][0]);
    const uint32_t xs1 = smem_u32(&xs[1][0][0]);
    const uint32_t h1b0 = smem_u32(&h1sm[0][0][0]);
    const uint32_t h1b1 = smem_u32(&h1sm[1][0][0]);
    const uint32_t h2b0 = smem_u32(&h2sm[0][0][0]);
    const uint32_t h2b1 = smem_u32(&h2sm[1][0][0]);
    const uint32_t a_lane_x = (uint32_t)((lid & 15) * 240 + (lid >> 4) * 16);
    const uint32_t a_lane_h = (uint32_t)((lid & 15) * 144 + (lid >> 4) * 16);

    auto stage_x = [&](int buf, int t) {
        const uint32_t dbase = buf ? xs1 : xs0;
        for (int idx = tid; idx < 32 * 14; idx += 256) {
            int row = idx / 14, ch = idx - row * 14;
            cpa16(dbase + row * 240 + ch * 16,
                  g_embbf + (size_t)toks[row * SEQLEN + t] * 128 + ch * 8);
        }
    };

    // prologue: stage x(0)
    stage_x(0, 0);
    CPA_COMMIT();
    CPA_WAIT0();
    __syncthreads();

    float cst1[2][2][2], cst2[2][2][2];
    #pragma unroll
    for (int mt = 0; mt < 2; mt++)
        for (int rs = 0; rs < 2; rs++)
            for (int uu = 0; uu < 2; uu++) { cst1[mt][rs][uu] = 0.f; cst2[mt][rs][uu] = 0.f; }

    float (*hfin)[68] = reinterpret_cast<float(*)[68]>(&xs[0][0][0]);  // alias; live only at t=80

    int p = 0;
    for (int t = 0; t <= SEQLEN; ++t) {
        const uint32_t h1rd = p ? h1b1 : h1b0;

        // -------------------- layer 1: h1(t) --------------------
        if (t < SEQLEN) {
            if (t + 1 < SEQLEN) { stage_x((t + 1) & 1, t + 1); }
            CPA_COMMIT();

            float acc[2][4][4];
            #pragma unroll
            for (int mt = 0; mt < 2; mt++)
                #pragma unroll
                for (int gg = 0; gg < 4; gg++) {
                    const int col = gg * 64 + wid * 8 + t4 * 2;
                    acc[mt][gg][0] = bsm[0][col]; acc[mt][gg][1] = bsm[0][col + 1];
                    acc[mt][gg][2] = acc[mt][gg][0]; acc[mt][gg][3] = acc[mt][gg][1];
                }
            const uint32_t xb = (t & 1) ? xs1 : xs0;
            #pragma unroll
            for (int kt = 0; kt < 7; kt++) {
                uint32_t a0[4], a1[4];
                ldmx4(a0, xb + a_lane_x + (uint32_t)(kt * 32));
                ldmx4(a1, xb + a_lane_x + (uint32_t)(16 * 240 + kt * 32));
                #pragma unroll
                for (int gg = 0; gg < 4; gg++) {
                    mma16816(acc[0][gg], a0, bw1[gg][kt]);
                    mma16816(acc[1][gg], a1, bw1[gg][kt]);
                }
            }
            #pragma unroll
            for (int kt = 0; kt < 4; kt++) {
                uint32_t a0[4], a1[4];
                ldmx4(a0, h1rd + a_lane_h + (uint32_t)(kt * 32));
                ldmx4(a1, h1rd + a_lane_h + (uint32_t)(16 * 144 + kt * 32));
                #pragma unroll
                for (int gg = 0; gg < 4; gg++) {
                    mma16816(acc[0][gg], a0, bu1[gg][kt]);
                    mma16816(acc[1][gg], a1, bu1[gg][kt]);
                }
            }
            #pragma unroll
            for (int mt = 0; mt < 2; mt++)
                #pragma unroll
                for (int rs = 0; rs < 2; rs++) {
                    const int row = mt * 16 + g + rs * 8;
                    float hv0, hv1;
                    {
                        float zi = acc[mt][0][rs * 2], zf = acc[mt][1][rs * 2];
                        float zg = acc[mt][2][rs * 2], zo = acc[mt][3][rs * 2];
                        float cn = sigf(zf) * cst1[mt][rs][0] + sigf(zi) * tanhapx(zg);
                        cst1[mt][rs][0] = cn;
                        hv0 = sigf(zo) * tanhapx(cn);
                    }
                    {
                        float zi = acc[mt][0][rs * 2 + 1], zf = acc[mt][1][rs * 2 + 1];
                        float zg = acc[mt][2][rs * 2 + 1], zo = acc[mt][3][rs * 2 + 1];
                        float cn = sigf(zf) * cst1[mt][rs][1] + sigf(zi) * tanhapx(zg);
                        cst1[mt][rs][1] = cn;
                        hv1 = sigf(zo) * tanhapx(cn);
                    }
                    *(__nv_bfloat162*)&h1sm[p ^ 1][row][wid * 8 + t4 * 2] =
                        __float22bfloat162_rn(make_float2(hv0, hv1));
                }
        }

        // -------------------- layer 2: h2(t-1) --------------------
        if (t >= 1) {
            const uint32_t h2rd = p ? h2b1 : h2b0;
            float acc[2][4][4];
            #pragma unroll
            for (int mt = 0; mt < 2; mt++)
                #pragma unroll
                for (int gg = 0; gg < 4; gg++) {
                    const int col = gg * 64 + wid * 8 + t4 * 2;
                    acc[mt][gg][0] = bsm[1][col]; acc[mt][gg][1] = bsm[1][col + 1];
                    acc[mt][gg][2] = acc[mt][gg][0]; acc[mt][gg][3] = acc[mt][gg][1];
                }
            #pragma unroll
            for (int kt = 0; kt < 4; kt++) {
                uint32_t a0[4], a1[4];
                ldmx4(a0, h1rd + a_lane_h + (uint32_t)(kt * 32));
                ldmx4(a1, h1rd + a_lane_h + (uint32_t)(16 * 144 + kt * 32));
                #pragma unroll
                for (int gg = 0; gg < 4; gg++) {
                    mma16816(acc[0][gg], a0, bw2[gg][kt]);
                    mma16816(acc[1][gg], a1, bw2[gg][kt]);
                }
            }
            #pragma unroll
            for (int kt = 0; kt < 4; kt++) {
                uint32_t a0[4], a1[4];
                ldmx4(a0, h2rd + a_lane_h + (uint32_t)(kt * 32));
                ldmx4(a1, h2rd + a_lane_h + (uint32_t)(16 * 144 + kt * 32));
                #pragma unroll
                for (int gg = 0; gg < 4; gg++) {
                    mma16816(acc[0][gg], a0, bu2[gg][kt]);
                    mma16816(acc[1][gg], a1, bu2[gg][kt]);
                }
            }
            #pragma unroll
            for (int mt = 0; mt < 2; mt++)
                #pragma unroll
                for (int rs = 0; rs < 2; rs++) {
                    const int row = mt * 16 + g + rs * 8;
                    float hv0, hv1;
                    {
                        float zi = acc[mt][0][rs * 2], zf = acc[mt][1][rs * 2];
                        float zg = acc[mt][2][rs * 2], zo = acc[mt][3][rs * 2];
                        float cn = sigf(zf) * cst2[mt][rs][0] + sigf(zi) * tanhapx(zg);
                        cst2[mt][rs][0] = cn;
                        hv0 = sigf(zo) * tanhapx(cn);
                    }
                    {
                        float zi = acc[mt][0][rs * 2 + 1], zf = acc[mt][1][rs * 2 + 1];
                        float zg = acc[mt][2][rs * 2 + 1], zo = acc[mt][3][rs * 2 + 1];
                        float cn = sigf(zf) * cst2[mt][rs][1] + sigf(zi) * tanhapx(zg);
                        cst2[mt][rs][1] = cn;
                        hv1 = sigf(zo) * tanhapx(cn);
                    }
                    if (t == SEQLEN) {
                        hfin[row][wid * 8 + t4 * 2]     = hv0;
                        hfin[row][wid * 8 + t4 * 2 + 1] = hv1;
                    } else {
                        *(__nv_bfloat162*)&h2sm[p ^ 1][row][wid * 8 + t4 * 2] =
                            __float22bfloat162_rn(make_float2(hv0, hv1));
                    }
                }
        }

        CPA_WAIT0();
        __syncthreads();
        p ^= 1;
    }

    // -------------------- dense head: out[b] = sigmoid(h2 . Wd + bd) -------
    if (tid < 32) {
        float s = bd[0];
        #pragma unroll
        for (int u = 0; u < 64; u++) s += hfin[tid][u] * Wd[u];
        out[b0 + tid] = fmaf(0.5f, tanhapx(0.5f * s), 0.5f);
    }
}

// ---------------------------------------------------------------------------
extern "C" void kernel_launch(void* const* d_in, const int* in_sizes, int n_in,
                              void* d_out, int out_size)
{
    const int*   tokens = (const int*)  d_in[0];
    const float* emb    = (const float*)d_in[1];
    const float* W1     = (const float*)d_in[2];
    const float* U1     = (const float*)d_in[3];
    const float* b1     = (const float*)d_in[4];
    const float* W2     = (const float*)d_in[5];
    const float* U2     = (const float*)d_in[6];
    const float* b2     = (const float*)d_in[7];
    const float* Wd     = (const float*)d_in[8];
    const float* bd     = (const float*)d_in[9];
    float* out = (float*)d_out;

    // one-time bf16 conversions (zero-padded where needed)
    conv_emb_kernel<<<10000 * 128 / 256, 256>>>(emb);
    conv_w1_kernel<<<256 * 128 / 256, 256>>>(W1);
    conv_w2_kernel<<<256 * 64 / 256, 256>>>(W2);

    // everything else: one fused kernel (both layers + dense head)
    lstm_both<<<BATCHN / 32, 256>>>(tokens, U1, b1, U2, b2, Wd, bd, out);
}

// round 9
// speedup vs baseline: 1.2199x; 1.1758x over previous
#include <cuda_runtime.h>
#include <cuda_bf16.h>
#include <cuda_fp16.h>
#include <cstdint>

#define BATCHN 4096
#define SEQLEN 80
#define EMBD   100
#define UNITS  64
#define NG     256                 // 4*UNITS gates
#define PROWS  (79 * 128)          // 10112 (vocab padded to m-tiles)

// ---------------- device scratch (allocation-free: device globals) ----------
__device__ __nv_bfloat16 g_embbf[10000 * 128];           // emb->bf16, K padded to 128
__device__ __nv_bfloat16 g_Wt1  [256 * 128];             // W1^T bf16 [n][k], k padded
__device__ uint16_t      g_P    [(size_t)PROWS * 256];   // f16 table: emb@W1 + b1

// ---------------- helpers ---------------------------------------------------
__device__ __forceinline__ float tanhapx(float x) {
    float y; asm("tanh.approx.f32 %0, %1;" : "=f"(y) : "f"(x)); return y;
}
__device__ __forceinline__ uint32_t smem_u32(const void* p) {
    uint32_t a;
    asm("{ .reg .u64 t; cvta.to.shared.u64 t, %1; cvt.u32.u64 %0, t; }" : "=r"(a) : "l"(p));
    return a;
}
// f16x2 ops (sm_75+; not arch-gated)
__device__ __forceinline__ uint32_t hmul2(uint32_t a, uint32_t b) {
    uint32_t d; asm("mul.rn.f16x2 %0,%1,%2;" : "=r"(d) : "r"(a), "r"(b)); return d;
}
__device__ __forceinline__ uint32_t hfma2(uint32_t a, uint32_t b, uint32_t c) {
    uint32_t d; asm("fma.rn.f16x2 %0,%1,%2,%3;" : "=r"(d) : "r"(a), "r"(b), "r"(c)); return d;
}
__device__ __forceinline__ uint32_t htanh2(uint32_t a) {
    uint32_t d; asm("tanh.approx.f16x2 %0,%1;" : "=r"(d) : "r"(a)); return d;
}
// pack two f32 -> f16x2 (lo, hi); PTX first src operand is HIGH half
__device__ __forceinline__ uint32_t packh(float lo, float hi) {
    uint32_t d; asm("cvt.rn.f16x2.f32 %0,%1,%2;" : "=r"(d) : "f"(hi), "f"(lo)); return d;
}
__device__ __forceinline__ float2 h2tof2(uint32_t h) {
    float lo, hi;
    asm("{ .reg .b16 l,h; mov.b32 {l,h}, %2; cvt.f32.f16 %0, l; cvt.f32.f16 %1, h; }"
        : "=f"(lo), "=f"(hi) : "r"(h));
    return make_float2(lo, hi);
}
// bf16 HMMA (for the P-table GEMM)
__device__ __forceinline__ void mma16816(float* d, const uint32_t* a, const uint32_t* b) {
    asm volatile(
        "mma.sync.aligned.m16n8k16.row.col.f32.bf16.bf16.f32 "
        "{%0,%1,%2,%3}, {%4,%5,%6,%7}, {%8,%9}, {%0,%1,%2,%3};"
        : "+f"(d[0]), "+f"(d[1]), "+f"(d[2]), "+f"(d[3])
        : "r"(a[0]), "r"(a[1]), "r"(a[2]), "r"(a[3]), "r"(b[0]), "r"(b[1]));
}
// f16 HMMA (scan: h and weights are f16)
__device__ __forceinline__ void mma16816h(float* d, const uint32_t* a, const uint32_t* b) {
    asm volatile(
        "mma.sync.aligned.m16n8k16.row.col.f32.f16.f16.f32 "
        "{%0,%1,%2,%3}, {%4,%5,%6,%7}, {%8,%9}, {%0,%1,%2,%3};"
        : "+f"(d[0]), "+f"(d[1]), "+f"(d[2]), "+f"(d[3])
        : "r"(a[0]), "r"(a[1]), "r"(a[2]), "r"(a[3]), "r"(b[0]), "r"(b[1]));
}
__device__ __forceinline__ void ldmx4(uint32_t* r, uint32_t addr) {
    asm volatile("ldmatrix.sync.aligned.m8n8.x4.shared.b16 {%0,%1,%2,%3}, [%4];"
        : "=r"(r[0]), "=r"(r[1]), "=r"(r[2]), "=r"(r[3]) : "r"(addr));
}
__device__ __forceinline__ void cpa16(uint32_t dst, const void* gsrc) {
    asm volatile("{ .reg .u64 ga; cvta.to.global.u64 ga, %1; "
                 "cp.async.ca.shared.global [%0], [ga], 16; }"
                 :: "r"(dst), "l"(gsrc) : "memory");
}
#define CPA_COMMIT() asm volatile("cp.async.commit_group;" ::: "memory")
#define CPA_WAIT0()  asm volatile("cp.async.wait_group 0;" ::: "memory")

// f16x2 LSTM cell pair: returns h (f16x2), updates c (f16x2)
__device__ __forceinline__ uint32_t lstm_cell2(
    float zi0, float zi1, float zf0, float zf1,
    float zg0, float zg1, float zo0, float zo1, uint32_t& c2)
{
    const uint32_t H05 = 0x38003800u;   // (0.5, 0.5) f16x2
    uint32_t si = hfma2(htanh2(hmul2(packh(zi0, zi1), H05)), H05, H05);
    uint32_t sf = hfma2(htanh2(hmul2(packh(zf0, zf1), H05)), H05, H05);
    uint32_t tg = htanh2(packh(zg0, zg1));
    uint32_t so = hfma2(htanh2(hmul2(packh(zo0, zo1), H05)), H05, H05);
    c2 = hfma2(sf, c2, hmul2(si, tg));
    return hmul2(so, htanh2(c2));
}

// ---------------------------------------------------------------------------
// Pre-conversion kernels
// ---------------------------------------------------------------------------
__global__ void conv_emb_kernel(const float* __restrict__ emb) {
    int idx = blockIdx.x * 256 + threadIdx.x;           // over 10000*128
    int v = idx >> 7, c = idx & 127;
    g_embbf[idx] = (c < EMBD) ? __float2bfloat16(emb[v * EMBD + c]) : __nv_bfloat16(0.f);
}
__global__ void conv_w1_kernel(const float* __restrict__ W) {
    int idx = blockIdx.x * 256 + threadIdx.x;           // over 256*128
    int n = idx >> 7, c = idx & 127;
    g_Wt1[idx] = (c < EMBD) ? __float2bfloat16(W[c * NG + n]) : __nv_bfloat16(0.f);
}

// ---------------------------------------------------------------------------
// P-table GEMM: P[v][0:256] = emb[v]@W1 + b1  (f16 out). Grid (2, 79).
// Same proven HMMA structure as R5 (K=112, 8 warps, warp tile 32x64).
// ---------------------------------------------------------------------------
__global__ void __launch_bounds__(256, 2) gemm_P(const float* __restrict__ bias)
{
    constexpr int K = 112, SA = K + 8, KH = K / 2;
    extern __shared__ __nv_bfloat16 smbf[];
    __nv_bfloat16* Asm = smbf;
    __nv_bfloat16* Bsm = smbf + 128 * SA;

    const int tid = threadIdx.x;
    const int m0  = blockIdx.y * 128;
    const int c0  = blockIdx.x * 128;

    for (int idx = tid; idx < 128 * KH; idx += 256) {
        int row = idx / KH, kc = (idx - row * KH) * 2;
        int m = m0 + row; if (m > 9999) m = 9999;
        *(uint32_t*)&Asm[row * SA + kc] = *(const uint32_t*)&g_embbf[(size_t)m * 128 + kc];
    }
    for (int idx = tid; idx < 128 * KH; idx += 256) {
        int row = idx / KH, kc = (idx - row * KH) * 2;
        *(uint32_t*)&Bsm[row * SA + kc] = *(const uint32_t*)&g_Wt1[(size_t)(c0 + row) * 128 + kc];
    }
    __syncthreads();

    const int wid  = tid >> 5, lid = tid & 31;
    const int wrow = wid & 3, wcol = wid >> 2;
    const int g    = lid >> 2, t = lid & 3;

    const uint32_t a_base = smem_u32(Asm);
    const uint32_t b_base = smem_u32(Bsm);
    const uint32_t a_lane = (uint32_t)((wrow * 32 + (lid & 15)) * SA * 2 + (lid >> 4) * 16);
    const uint32_t b_lane = (uint32_t)((wcol * 64 + (lid >> 4) * 8 + (lid & 7)) * SA * 2 +
                                       ((lid >> 3) & 1) * 16);

    float acc[2][8][4];
    #pragma unroll
    for (int mt = 0; mt < 2; mt++)
        #pragma unroll
        for (int nt = 0; nt < 8; nt++)
            #pragma unroll
            for (int r = 0; r < 4; r++) acc[mt][nt][r] = 0.f;

    #pragma unroll
    for (int s = 0; s < K / 16; s++) {
        uint32_t af[2][4], bfr[8][2];
        #pragma unroll
        for (int mt = 0; mt < 2; mt++)
            ldmx4(af[mt], a_base + a_lane + (uint32_t)(mt * 16 * SA * 2 + s * 32));
        #pragma unroll
        for (int np = 0; np < 4; np++) {
            uint32_t bq[4];
            ldmx4(bq, b_base + b_lane + (uint32_t)(np * 16 * SA * 2 + s * 32));
            bfr[np * 2][0] = bq[0]; bfr[np * 2][1] = bq[1];
            bfr[np * 2 + 1][0] = bq[2]; bfr[np * 2 + 1][1] = bq[3];
        }
        #pragma unroll
        for (int mt = 0; mt < 2; mt++)
            #pragma unroll
            for (int nt = 0; nt < 8; nt++)
                mma16816(acc[mt][nt], af[mt], bfr[nt]);
    }

    #pragma unroll
    for (int nt = 0; nt < 8; nt++) {
        const int col = c0 + wcol * 64 + nt * 8 + t * 2;
        float2 bb = *(const float2*)&bias[col];
        #pragma unroll
        for (int mt = 0; mt < 2; mt++) {
            const int row = m0 + wrow * 32 + mt * 16 + g;
            *(uint32_t*)&g_P[(size_t)row * 256 + col] =
                packh(acc[mt][nt][0] + bb.x, acc[mt][nt][1] + bb.y);
            *(uint32_t*)&g_P[(size_t)(row + 8) * 256 + col] =
                packh(acc[mt][nt][2] + bb.x, acc[mt][nt][3] + bb.y);
        }
    }
}

// ---------------------------------------------------------------------------
// Fused scan: both layers + dense head. 128 CTAs x 256 thr, 32 rows/CTA.
// Layer1 z = P[token] (gathered f16, no mma) + h1@U1 (4 mma-kt).
// Layer2 (lag 1) z = b2 + h1@W2 + h2@U2 (8 mma-kt). Gates in f16x2 (MUFU h2).
// h state f16 in SMEM; c f16x2 in regs; one __syncthreads per step.
// ---------------------------------------------------------------------------
// smem layout (bytes)
#define XS_OFF  0                      // 2 x 32 x 528   = 33792 (f16 P rows, pad 264)
#define H1_OFF  33792                  // 2 x 32 x 144   = 9216
#define H2_OFF  43008                  // 9216
#define TOK_OFF 52224                  // 32 x 80 x 2    = 5120
#define B2_OFF  57344                  // 256 x 4        = 1024
#define SM_TOTAL 58368

__global__ void __launch_bounds__(256, 1) lstm_both2(
    const int*   __restrict__ tokens,
    const float* __restrict__ U1,
    const float* __restrict__ W2,
    const float* __restrict__ U2,
    const float* __restrict__ b2,
    const float* __restrict__ Wd,
    const float* __restrict__ bd,
    float*       __restrict__ out)
{
    extern __shared__ char sm[];
    const int tid = threadIdx.x, wid = tid >> 5, lid = tid & 31;
    const int g = lid >> 2, t4 = lid & 3;
    const int b0 = blockIdx.x * 32;

    uint16_t* toks = (uint16_t*)(sm + TOK_OFF);
    float*    b2s  = (float*)(sm + B2_OFF);

    {   // zero h buffers
        uint32_t* z1 = (uint32_t*)(sm + H1_OFF);
        for (int i = tid; i < 2 * 9216 / 4; i += 256) z1[i] = 0u;
    }
    for (int idx = tid; idx < 32 * SEQLEN; idx += 256)
        toks[idx] = (uint16_t)tokens[(size_t)(b0 + idx / SEQLEN) * SEQLEN + idx % SEQLEN];
    for (int idx = tid; idx < NG; idx += 256) b2s[idx] = b2[idx];

    // ---- register B-fragments (f16): U1, W2, U2 ----
    uint32_t bu1[4][4][2], bw2[4][4][2], bu2[4][4][2];
    #pragma unroll
    for (int gg = 0; gg < 4; gg++) {
        const int n = gg * 64 + wid * 8 + g;
        #pragma unroll
        for (int kt = 0; kt < 4; kt++) {
            const int k0 = kt * 16 + t4 * 2;
            bu1[gg][kt][0] = packh(U1[(size_t)k0 * NG + n],       U1[(size_t)(k0 + 1) * NG + n]);
            bu1[gg][kt][1] = packh(U1[(size_t)(k0 + 8) * NG + n], U1[(size_t)(k0 + 9) * NG + n]);
            bw2[gg][kt][0] = packh(W2[(size_t)k0 * NG + n],       W2[(size_t)(k0 + 1) * NG + n]);
            bw2[gg][kt][1] = packh(W2[(size_t)(k0 + 8) * NG + n], W2[(size_t)(k0 + 9) * NG + n]);
            bu2[gg][kt][0] = packh(U2[(size_t)k0 * NG + n],       U2[(size_t)(k0 + 1) * NG + n]);
            bu2[gg][kt][1] = packh(U2[(size_t)(k0 + 8) * NG + n], U2[(size_t)(k0 + 9) * NG + n]);
        }
    }
    __syncthreads();   // toks/b2s/zeroed h visible

    const uint32_t xs_b  = smem_u32(sm + XS_OFF);
    const uint32_t h1b0  = smem_u32(sm + H1_OFF);
    const uint32_t h1b1  = h1b0 + 4608;
    const uint32_t h2b0  = smem_u32(sm + H2_OFF);
    const uint32_t h2b1  = h2b0 + 4608;
    const uint32_t a_lane_h = (uint32_t)((lid & 15) * 144 + (lid >> 4) * 16);
    const int colb = (wid * 8 + t4 * 2) * 2;   // byte offset of this thread's unit pair

    auto stage_x = [&](int buf, int t) {
        const uint32_t dbase = xs_b + buf * 16896;
        #pragma unroll
        for (int i = 0; i < 4; i++) {
            int idx = tid + i * 256;           // over 32 rows x 32 chunks
            int row = idx >> 5, ch = idx & 31;
            cpa16(dbase + row * 528 + ch * 16,
                  g_P + (size_t)toks[row * SEQLEN + t] * 256 + ch * 8);
        }
    };

    // prologue: stage x(0)
    stage_x(0, 0);
    CPA_COMMIT();
    CPA_WAIT0();
    __syncthreads();

    uint32_t c1[2][2], c2s[2][2];
    #pragma unroll
    for (int mt = 0; mt < 2; mt++)
        for (int rs = 0; rs < 2; rs++) { c1[mt][rs] = 0u; c2s[mt][rs] = 0u; }

    float (*hfin)[68] = reinterpret_cast<float(*)[68]>(sm + XS_OFF);  // alias, live at t=80

    int p = 0;
    for (int t = 0; t <= SEQLEN; ++t) {
        const uint32_t h1rd = p ? h1b1 : h1b0;

        // -------------------- layer 1: h1(t) --------------------
        if (t < SEQLEN) {
            if (t + 1 < SEQLEN) stage_x((t + 1) & 1, t + 1);
            CPA_COMMIT();

            float acc[2][4][4];
            const char* xb = sm + XS_OFF + (t & 1) * 16896;
            #pragma unroll
            for (int mt = 0; mt < 2; mt++)
                #pragma unroll
                for (int gg = 0; gg < 4; gg++)
                    #pragma unroll
                    for (int rs = 0; rs < 2; rs++) {
                        uint32_t v = *(const uint32_t*)(xb + (mt * 16 + g + rs * 8) * 528 +
                                                        gg * 128 + colb);
                        float2 f = h2tof2(v);
                        acc[mt][gg][rs * 2] = f.x; acc[mt][gg][rs * 2 + 1] = f.y;
                    }
            #pragma unroll
            for (int kt = 0; kt < 4; kt++) {
                uint32_t a0[4], a1[4];
                ldmx4(a0, h1rd + a_lane_h + (uint32_t)(kt * 32));
                ldmx4(a1, h1rd + a_lane_h + (uint32_t)(16 * 144 + kt * 32));
                #pragma unroll
                for (int gg = 0; gg < 4; gg++) {
                    mma16816h(acc[0][gg], a0, bu1[gg][kt]);
                    mma16816h(acc[1][gg], a1, bu1[gg][kt]);
                }
            }
            char* h1wr = sm + H1_OFF + (p ^ 1) * 4608;
            #pragma unroll
            for (int mt = 0; mt < 2; mt++)
                #pragma unroll
                for (int rs = 0; rs < 2; rs++) {
                    uint32_t hv = lstm_cell2(
                        acc[mt][0][rs * 2], acc[mt][0][rs * 2 + 1],
                        acc[mt][1][rs * 2], acc[mt][1][rs * 2 + 1],
                        acc[mt][2][rs * 2], acc[mt][2][rs * 2 + 1],
                        acc[mt][3][rs * 2], acc[mt][3][rs * 2 + 1], c1[mt][rs]);
                    *(uint32_t*)(h1wr + (mt * 16 + g + rs * 8) * 144 + colb) = hv;
                }
        }

        // -------------------- layer 2: h2(t-1) --------------------
        if (t >= 1) {
            const uint32_t h2rd = p ? h2b1 : h2b0;
            float acc[2][4][4];
            #pragma unroll
            for (int mt = 0; mt < 2; mt++)
                #pragma unroll
                for (int gg = 0; gg < 4; gg++) {
                    const int col = gg * 64 + wid * 8 + t4 * 2;
                    acc[mt][gg][0] = b2s[col]; acc[mt][gg][1] = b2s[col + 1];
                    acc[mt][gg][2] = acc[mt][gg][0]; acc[mt][gg][3] = acc[mt][gg][1];
                }
            #pragma unroll
            for (int kt = 0; kt < 4; kt++) {
                uint32_t a0[4], a1[4];
                ldmx4(a0, h1rd + a_lane_h + (uint32_t)(kt * 32));
                ldmx4(a1, h1rd + a_lane_h + (uint32_t)(16 * 144 + kt * 32));
                #pragma unroll
                for (int gg = 0; gg < 4; gg++) {
                    mma16816h(acc[0][gg], a0, bw2[gg][kt]);
                    mma16816h(acc[1][gg], a1, bw2[gg][kt]);
                }
            }
            #pragma unroll
            for (int kt = 0; kt < 4; kt++) {
                uint32_t a0[4], a1[4];
                ldmx4(a0, h2rd + a_lane_h + (uint32_t)(kt * 32));
                ldmx4(a1, h2rd + a_lane_h + (uint32_t)(16 * 144 + kt * 32));
                #pragma unroll
                for (int gg = 0; gg < 4; gg++) {
                    mma16816h(acc[0][gg], a0, bu2[gg][kt]);
                    mma16816h(acc[1][gg], a1, bu2[gg][kt]);
                }
            }
            char* h2wr = sm + H2_OFF + (p ^ 1) * 4608;
            #pragma unroll
            for (int mt = 0; mt < 2; mt++)
                #pragma unroll
                for (int rs = 0; rs < 2; rs++) {
                    uint32_t hv = lstm_cell2(
                        acc[mt][0][rs * 2], acc[mt][0][rs * 2 + 1],
                        acc[mt][1][rs * 2], acc[mt][1][rs * 2 + 1],
                        acc[mt][2][rs * 2], acc[mt][2][rs * 2 + 1],
                        acc[mt][3][rs * 2], acc[mt][3][rs * 2 + 1], c2s[mt][rs]);
                    const int row = mt * 16 + g + rs * 8;
                    if (t == SEQLEN) {
                        float2 f = h2tof2(hv);
                        hfin[row][wid * 8 + t4 * 2]     = f.x;
                        hfin[row][wid * 8 + t4 * 2 + 1] = f.y;
                    } else {
                        *(uint32_t*)(h2wr + row * 144 + colb) = hv;
                    }
                }
        }

        CPA_WAIT0();
        __syncthreads();
        p ^= 1;
    }

    // -------------------- dense head -------------------------------------
    if (tid < 32) {
        float s = bd[0];
        #pragma unroll
        for (int u = 0; u < 64; u++) s += hfin[tid][u] * Wd[u];
        out[b0 + tid] = fmaf(0.5f, tanhapx(0.5f * s), 0.5f);
    }
}

// ---------------------------------------------------------------------------
extern "C" void kernel_launch(void* const* d_in, const int* in_sizes, int n_in,
                              void* d_out, int out_size)
{
    const int*   tokens = (const int*)  d_in[0];
    const float* emb    = (const float*)d_in[1];
    const float* W1     = (const float*)d_in[2];
    const float* U1     = (const float*)d_in[3];
    const float* b1     = (const float*)d_in[4];
    const float* W2     = (const float*)d_in[5];
    const float* U2     = (const float*)d_in[6];
    const float* b2     = (const float*)d_in[7];
    const float* Wd     = (const float*)d_in[8];
    const float* bd     = (const float*)d_in[9];
    float* out = (float*)d_out;

    const int smem_gp = 2 * 128 * (112 + 8) * 2;   // 61440
    cudaFuncSetAttribute(gemm_P,     cudaFuncAttributeMaxDynamicSharedMemorySize, smem_gp);
    cudaFuncSetAttribute(lstm_both2, cudaFuncAttributeMaxDynamicSharedMemorySize, SM_TOTAL);

    // one-time conversions + P table (emb@W1 + b1, f16)
    conv_emb_kernel<<<10000 * 128 / 256, 256>>>(emb);
    conv_w1_kernel<<<256 * 128 / 256, 256>>>(W1);
    dim3 pgrid(2, 79);
    gemm_P<<<pgrid, 256, smem_gp>>>(b1);

    // both layers + dense head, one kernel
    lstm_both2<<<BATCHN / 32, 256, SM_TOTAL>>>(tokens, U1, W2, U2, b2, Wd, bd, out);
}

// round 10
// speedup vs baseline: 1.3849x; 1.1353x over previous
#include <cuda_runtime.h>
#include <cuda_bf16.h>
#include <cuda_fp16.h>
#include <cstdint>

#define BATCHN 4096
#define SEQLEN 80
#define EMBD   100
#define UNITS  64
#define NG     256                 // 4*UNITS gates
#define PROWS  (79 * 128)          // vocab padded to m-tiles

// ---------------- device scratch (allocation-free: device globals) ----------
__device__ __nv_bfloat16 g_embbf[10000 * 128];           // emb->bf16, K padded to 128
__device__ __nv_bfloat16 g_Wt1  [256 * 128];             // W1^T bf16 [n][k], k padded
__device__ uint16_t      g_P    [(size_t)PROWS * 256];   // f16 table: emb@W1 + b1

// ---------------- helpers ---------------------------------------------------
__device__ __forceinline__ float tanhapx(float x) {
    float y; asm("tanh.approx.f32 %0, %1;" : "=f"(y) : "f"(x)); return y;
}
__device__ __forceinline__ uint32_t smem_u32(const void* p) {
    uint32_t a;
    asm("{ .reg .u64 t; cvta.to.shared.u64 t, %1; cvt.u32.u64 %0, t; }" : "=r"(a) : "l"(p));
    return a;
}
// f16x2 ops
__device__ __forceinline__ uint32_t hmul2(uint32_t a, uint32_t b) {
    uint32_t d; asm("mul.rn.f16x2 %0,%1,%2;" : "=r"(d) : "r"(a), "r"(b)); return d;
}
__device__ __forceinline__ uint32_t hfma2(uint32_t a, uint32_t b, uint32_t c) {
    uint32_t d; asm("fma.rn.f16x2 %0,%1,%2,%3;" : "=r"(d) : "r"(a), "r"(b), "r"(c)); return d;
}
__device__ __forceinline__ uint32_t htanh2(uint32_t a) {
    uint32_t d; asm("tanh.approx.f16x2 %0,%1;" : "=r"(d) : "r"(a)); return d;
}
__device__ __forceinline__ uint32_t packh(float lo, float hi) {
    uint32_t d; asm("cvt.rn.f16x2.f32 %0,%1,%2;" : "=r"(d) : "f"(hi), "f"(lo)); return d;
}
__device__ __forceinline__ float2 h2tof2(uint32_t h) {
    float lo, hi;
    asm("{ .reg .b16 l,h; mov.b32 {l,h}, %2; cvt.f32.f16 %0, l; cvt.f32.f16 %1, h; }"
        : "=f"(lo), "=f"(hi) : "r"(h));
    return make_float2(lo, hi);
}
// bf16 HMMA, f32 acc (P-table GEMM only)
__device__ __forceinline__ void mma16816(float* d, const uint32_t* a, const uint32_t* b) {
    asm volatile(
        "mma.sync.aligned.m16n8k16.row.col.f32.bf16.bf16.f32 "
        "{%0,%1,%2,%3}, {%4,%5,%6,%7}, {%8,%9}, {%0,%1,%2,%3};"
        : "+f"(d[0]), "+f"(d[1]), "+f"(d[2]), "+f"(d[3])
        : "r"(a[0]), "r"(a[1]), "r"(a[2]), "r"(a[3]), "r"(b[0]), "r"(b[1]));
}
// f16 HMMA, f16 acc (scan): d regs are f16x2 col-pairs, rows g / g+8
__device__ __forceinline__ void mma16816hh(uint32_t* d, const uint32_t* a, const uint32_t* b) {
    asm volatile(
        "mma.sync.aligned.m16n8k16.row.col.f16.f16.f16.f16 "
        "{%0,%1}, {%2,%3,%4,%5}, {%6,%7}, {%0,%1};"
        : "+r"(d[0]), "+r"(d[1])
        : "r"(a[0]), "r"(a[1]), "r"(a[2]), "r"(a[3]), "r"(b[0]), "r"(b[1]));
}
__device__ __forceinline__ void ldmx4(uint32_t* r, uint32_t addr) {
    asm volatile("ldmatrix.sync.aligned.m8n8.x4.shared.b16 {%0,%1,%2,%3}, [%4];"
        : "=r"(r[0]), "=r"(r[1]), "=r"(r[2]), "=r"(r[3]) : "r"(addr));
}
__device__ __forceinline__ void cpa16(uint32_t dst, const void* gsrc) {
    asm volatile("{ .reg .u64 ga; cvta.to.global.u64 ga, %1; "
                 "cp.async.ca.shared.global [%0], [ga], 16; }"
                 :: "r"(dst), "l"(gsrc) : "memory");
}
#define CPA_COMMIT() asm volatile("cp.async.commit_group;" ::: "memory")
#define CPA_WAIT0()  asm volatile("cp.async.wait_group 0;" ::: "memory")

// f16x2 LSTM cell pair: z inputs already f16x2 (col pair); updates c in-place
__device__ __forceinline__ uint32_t lstm_cell2h(
    uint32_t zi, uint32_t zf, uint32_t zg, uint32_t zo, uint32_t& c2)
{
    const uint32_t H05 = 0x38003800u;   // (0.5, 0.5)
    uint32_t si = hfma2(htanh2(hmul2(zi, H05)), H05, H05);
    uint32_t sf = hfma2(htanh2(hmul2(zf, H05)), H05, H05);
    uint32_t tg = htanh2(zg);
    uint32_t so = hfma2(htanh2(hmul2(zo, H05)), H05, H05);
    c2 = hfma2(sf, c2, hmul2(si, tg));
    return hmul2(so, htanh2(c2));
}

// ---------------------------------------------------------------------------
// Pre-conversion kernels
// ---------------------------------------------------------------------------
__global__ void conv_emb_kernel(const float* __restrict__ emb) {
    int idx = blockIdx.x * 256 + threadIdx.x;
    int v = idx >> 7, c = idx & 127;
    g_embbf[idx] = (c < EMBD) ? __float2bfloat16(emb[v * EMBD + c]) : __nv_bfloat16(0.f);
}
__global__ void conv_w1_kernel(const float* __restrict__ W) {
    int idx = blockIdx.x * 256 + threadIdx.x;
    int n = idx >> 7, c = idx & 127;
    g_Wt1[idx] = (c < EMBD) ? __float2bfloat16(W[c * NG + n]) : __nv_bfloat16(0.f);
}

// ---------------------------------------------------------------------------
// P-table GEMM: P[v][0:256] = emb[v]@W1 + b1 (f16 out). Grid (2, 79).
// ---------------------------------------------------------------------------
__global__ void __launch_bounds__(256, 2) gemm_P(const float* __restrict__ bias)
{
    constexpr int K = 112, SA = K + 8, KH = K / 2;
    extern __shared__ __nv_bfloat16 smbf[];
    __nv_bfloat16* Asm = smbf;
    __nv_bfloat16* Bsm = smbf + 128 * SA;

    const int tid = threadIdx.x;
    const int m0  = blockIdx.y * 128;
    const int c0  = blockIdx.x * 128;

    for (int idx = tid; idx < 128 * KH; idx += 256) {
        int row = idx / KH, kc = (idx - row * KH) * 2;
        int m = m0 + row; if (m > 9999) m = 9999;
        *(uint32_t*)&Asm[row * SA + kc] = *(const uint32_t*)&g_embbf[(size_t)m * 128 + kc];
    }
    for (int idx = tid; idx < 128 * KH; idx += 256) {
        int row = idx / KH, kc = (idx - row * KH) * 2;
        *(uint32_t*)&Bsm[row * SA + kc] = *(const uint32_t*)&g_Wt1[(size_t)(c0 + row) * 128 + kc];
    }
    __syncthreads();

    const int wid  = tid >> 5, lid = tid & 31;
    const int wrow = wid & 3, wcol = wid >> 2;
    const int g    = lid >> 2, t = lid & 3;

    const uint32_t a_base = smem_u32(Asm);
    const uint32_t b_base = smem_u32(Bsm);
    const uint32_t a_lane = (uint32_t)((wrow * 32 + (lid & 15)) * SA * 2 + (lid >> 4) * 16);
    const uint32_t b_lane = (uint32_t)((wcol * 64 + (lid >> 4) * 8 + (lid & 7)) * SA * 2 +
                                       ((lid >> 3) & 1) * 16);

    float acc[2][8][4];
    #pragma unroll
    for (int mt = 0; mt < 2; mt++)
        #pragma unroll
        for (int nt = 0; nt < 8; nt++)
            #pragma unroll
            for (int r = 0; r < 4; r++) acc[mt][nt][r] = 0.f;

    #pragma unroll
    for (int s = 0; s < K / 16; s++) {
        uint32_t af[2][4], bfr[8][2];
        #pragma unroll
        for (int mt = 0; mt < 2; mt++)
            ldmx4(af[mt], a_base + a_lane + (uint32_t)(mt * 16 * SA * 2 + s * 32));
        #pragma unroll
        for (int np = 0; np < 4; np++) {
            uint32_t bq[4];
            ldmx4(bq, b_base + b_lane + (uint32_t)(np * 16 * SA * 2 + s * 32));
            bfr[np * 2][0] = bq[0]; bfr[np * 2][1] = bq[1];
            bfr[np * 2 + 1][0] = bq[2]; bfr[np * 2 + 1][1] = bq[3];
        }
        #pragma unroll
        for (int mt = 0; mt < 2; mt++)
            #pragma unroll
            for (int nt = 0; nt < 8; nt++)
                mma16816(acc[mt][nt], af[mt], bfr[nt]);
    }

    #pragma unroll
    for (int nt = 0; nt < 8; nt++) {
        const int col = c0 + wcol * 64 + nt * 8 + t * 2;
        float2 bb = *(const float2*)&bias[col];
        #pragma unroll
        for (int mt = 0; mt < 2; mt++) {
            const int row = m0 + wrow * 32 + mt * 16 + g;
            *(uint32_t*)&g_P[(size_t)row * 256 + col] =
                packh(acc[mt][nt][0] + bb.x, acc[mt][nt][1] + bb.y);
            *(uint32_t*)&g_P[(size_t)(row + 8) * 256 + col] =
                packh(acc[mt][nt][2] + bb.x, acc[mt][nt][3] + bb.y);
        }
    }
}

// ---------------------------------------------------------------------------
// Fused scan, f16 accumulators. 128 CTAs x 256 thr, 32 rows/CTA.
// L1: z = P[token] + h1@U1. L2 (lag 1): z = b2 + h1@W2 + h2@U2.
// h1 A-fragments loaded ONCE per step, shared by U1 and W2 mma.
// ---------------------------------------------------------------------------
#define XS_OFF  0                      // 2 x 32 x 528  = 33792 (f16 P rows)
#define H1_OFF  33792                  // 2 x 32 x 144  = 9216
#define H2_OFF  43008                  // 9216
#define TOK_OFF 52224                  // 32 x 80 x 2   = 5120
#define SM_TOTAL 57344

__global__ void __launch_bounds__(256, 1) lstm_both3(
    const int*   __restrict__ tokens,
    const float* __restrict__ U1,
    const float* __restrict__ W2,
    const float* __restrict__ U2,
    const float* __restrict__ b2,
    const float* __restrict__ Wd,
    const float* __restrict__ bd,
    float*       __restrict__ out)
{
    extern __shared__ char sm[];
    const int tid = threadIdx.x, wid = tid >> 5, lid = tid & 31;
    const int g = lid >> 2, t4 = lid & 3;
    const int b0 = blockIdx.x * 32;

    uint16_t* toks = (uint16_t*)(sm + TOK_OFF);

    {   // zero h buffers (h2 must be 0; h1 cheap to include)
        uint32_t* z1 = (uint32_t*)(sm + H1_OFF);
        for (int i = tid; i < 2 * 9216 / 4; i += 256) z1[i] = 0u;
    }
    for (int idx = tid; idx < 32 * SEQLEN; idx += 256)
        toks[idx] = (uint16_t)tokens[(size_t)(b0 + idx / SEQLEN) * SEQLEN + idx % SEQLEN];
    __syncthreads();

    const uint32_t xs_b = smem_u32(sm + XS_OFF);
    auto stage_x = [&](int buf, int t) {
        const uint32_t dbase = xs_b + buf * 16896;
        #pragma unroll
        for (int i = 0; i < 4; i++) {
            int idx = tid + i * 256;           // 32 rows x 32 chunks of 16B
            int row = idx >> 5, ch = idx & 31;
            cpa16(dbase + row * 528 + ch * 16,
                  g_P + (size_t)toks[row * SEQLEN + t] * 256 + ch * 8);
        }
    };

    // start x(0) fetch, then load weight fragments while it flies
    stage_x(0, 0);
    CPA_COMMIT();

    uint32_t bu1[4][4][2], bw2[4][4][2], bu2[4][4][2], rb2[4];
    #pragma unroll
    for (int gg = 0; gg < 4; gg++) {
        const int n = gg * 64 + wid * 8 + g;
        #pragma unroll
        for (int kt = 0; kt < 4; kt++) {
            const int k0 = kt * 16 + t4 * 2;
            bu1[gg][kt][0] = packh(U1[(size_t)k0 * NG + n],       U1[(size_t)(k0 + 1) * NG + n]);
            bu1[gg][kt][1] = packh(U1[(size_t)(k0 + 8) * NG + n], U1[(size_t)(k0 + 9) * NG + n]);
            bw2[gg][kt][0] = packh(W2[(size_t)k0 * NG + n],       W2[(size_t)(k0 + 1) * NG + n]);
            bw2[gg][kt][1] = packh(W2[(size_t)(k0 + 8) * NG + n], W2[(size_t)(k0 + 9) * NG + n]);
            bu2[gg][kt][0] = packh(U2[(size_t)k0 * NG + n],       U2[(size_t)(k0 + 1) * NG + n]);
            bu2[gg][kt][1] = packh(U2[(size_t)(k0 + 8) * NG + n], U2[(size_t)(k0 + 9) * NG + n]);
        }
        const int col = gg * 64 + wid * 8 + t4 * 2;
        rb2[gg] = packh(b2[col], b2[col + 1]);
    }

    const uint32_t h1b0 = smem_u32(sm + H1_OFF), h1b1 = h1b0 + 4608;
    const uint32_t h2b0 = smem_u32(sm + H2_OFF), h2b1 = h2b0 + 4608;
    const uint32_t a_lane_h = (uint32_t)((lid & 15) * 144 + (lid >> 4) * 16);
    const int colb = (wid * 8 + t4 * 2) * 2;

    uint32_t c1[2][2], c2s[2][2];
    #pragma unroll
    for (int mt = 0; mt < 2; mt++)
        for (int rs = 0; rs < 2; rs++) { c1[mt][rs] = 0u; c2s[mt][rs] = 0u; }

    CPA_WAIT0();
    __syncthreads();

    // ---- t = 0: h1(0) = cell(x(0)) (h1(-1)=0 -> no mma); stage x(1) ----
    stage_x(1, 1);
    CPA_COMMIT();
    {
        const char* xb = sm + XS_OFF;
        char* h1wr = sm + H1_OFF + 4608;           // buf1
        #pragma unroll
        for (int mt = 0; mt < 2; mt++)
            #pragma unroll
            for (int rs = 0; rs < 2; rs++) {
                const int row = mt * 16 + g + rs * 8;
                uint32_t z[4];
                #pragma unroll
                for (int gg = 0; gg < 4; gg++)
                    z[gg] = *(const uint32_t*)(xb + row * 528 + gg * 128 + colb);
                uint32_t hv = lstm_cell2h(z[0], z[1], z[2], z[3], c1[mt][rs]);
                *(uint32_t*)(h1wr + row * 144 + colb) = hv;
            }
    }
    CPA_WAIT0();
    __syncthreads();

    // ---- steady state: t = 1 .. 79 ----
    for (int t = 1; t < SEQLEN; ++t) {
        if (t + 1 < SEQLEN) stage_x((t + 1) & 1, t + 1);
        CPA_COMMIT();

        const uint32_t h1rd = (t & 1) ? h1b1 : h1b0;
        const uint32_t h2rd = (t & 1) ? h2b1 : h2b0;

        uint32_t acc1[2][4][2], acc2[2][4][2];
        const char* xb = sm + XS_OFF + (t & 1) * 16896;
        #pragma unroll
        for (int mt = 0; mt < 2; mt++)
            #pragma unroll
            for (int gg = 0; gg < 4; gg++) {
                acc1[mt][gg][0] = *(const uint32_t*)(xb + (mt * 16 + g) * 528 + gg * 128 + colb);
                acc1[mt][gg][1] = *(const uint32_t*)(xb + (mt * 16 + g + 8) * 528 + gg * 128 + colb);
                acc2[mt][gg][0] = rb2[gg];
                acc2[mt][gg][1] = rb2[gg];
            }

        // h1 fragments shared by U1 (layer1) and W2 (layer2)
        #pragma unroll
        for (int kt = 0; kt < 4; kt++) {
            uint32_t a0[4], a1[4];
            ldmx4(a0, h1rd + a_lane_h + (uint32_t)(kt * 32));
            ldmx4(a1, h1rd + a_lane_h + (uint32_t)(16 * 144 + kt * 32));
            #pragma unroll
            for (int gg = 0; gg < 4; gg++) {
                mma16816hh(acc1[0][gg], a0, bu1[gg][kt]);
                mma16816hh(acc2[0][gg], a0, bw2[gg][kt]);
                mma16816hh(acc1[1][gg], a1, bu1[gg][kt]);
                mma16816hh(acc2[1][gg], a1, bw2[gg][kt]);
            }
        }
        #pragma unroll
        for (int kt = 0; kt < 4; kt++) {
            uint32_t a0[4], a1[4];
            ldmx4(a0, h2rd + a_lane_h + (uint32_t)(kt * 32));
            ldmx4(a1, h2rd + a_lane_h + (uint32_t)(16 * 144 + kt * 32));
            #pragma unroll
            for (int gg = 0; gg < 4; gg++) {
                mma16816hh(acc2[0][gg], a0, bu2[gg][kt]);
                mma16816hh(acc2[1][gg], a1, bu2[gg][kt]);
            }
        }

        char* h1wr = sm + H1_OFF + ((t & 1) ^ 1) * 4608;
        char* h2wr = sm + H2_OFF + ((t & 1) ^ 1) * 4608;
        #pragma unroll
        for (int mt = 0; mt < 2; mt++)
            #pragma unroll
            for (int rs = 0; rs < 2; rs++) {
                const int row = mt * 16 + g + rs * 8;
                uint32_t hv1 = lstm_cell2h(acc1[mt][0][rs], acc1[mt][1][rs],
                                           acc1[mt][2][rs], acc1[mt][3][rs], c1[mt][rs]);
                *(uint32_t*)(h1wr + row * 144 + colb) = hv1;
                uint32_t hv2 = lstm_cell2h(acc2[mt][0][rs], acc2[mt][1][rs],
                                           acc2[mt][2][rs], acc2[mt][3][rs], c2s[mt][rs]);
                *(uint32_t*)(h2wr + row * 144 + colb) = hv2;
            }

        CPA_WAIT0();
        __syncthreads();
    }

    // ---- epilogue: h2(79) from h1(79), h2(78) (both in buf0) ----
    float (*hfin)[68] = reinterpret_cast<float(*)[68]>(sm + XS_OFF);
    {
        const uint32_t h1rd = h1b0, h2rd = h2b0;   // t = 80 -> buf 0
        uint32_t acc2[2][4][2];
        #pragma unroll
        for (int mt = 0; mt < 2; mt++)
            #pragma unroll
            for (int gg = 0; gg < 4; gg++) { acc2[mt][gg][0] = rb2[gg]; acc2[mt][gg][1] = rb2[gg]; }
        #pragma unroll
        for (int kt = 0; kt < 4; kt++) {
            uint32_t a0[4], a1[4];
            ldmx4(a0, h1rd + a_lane_h + (uint32_t)(kt * 32));
            ldmx4(a1, h1rd + a_lane_h + (uint32_t)(16 * 144 + kt * 32));
            #pragma unroll
            for (int gg = 0; gg < 4; gg++) {
                mma16816hh(acc2[0][gg], a0, bw2[gg][kt]);
                mma16816hh(acc2[1][gg], a1, bw2[gg][kt]);
            }
        }
        #pragma unroll
        for (int kt = 0; kt < 4; kt++) {
            uint32_t a0[4], a1[4];
            ldmx4(a0, h2rd + a_lane_h + (uint32_t)(kt * 32));
            ldmx4(a1, h2rd + a_lane_h + (uint32_t)(16 * 144 + kt * 32));
            #pragma unroll
            for (int gg = 0; gg < 4; gg++) {
                mma16816hh(acc2[0][gg], a0, bu2[gg][kt]);
                mma16816hh(acc2[1][gg], a1, bu2[gg][kt]);
            }
        }
        __syncthreads();   // xs reads long done; hfin aliases xs
        #pragma unroll
        for (int mt = 0; mt < 2; mt++)
            #pragma unroll
            for (int rs = 0; rs < 2; rs++) {
                const int row = mt * 16 + g + rs * 8;
                uint32_t hv = lstm_cell2h(acc2[mt][0][rs], acc2[mt][1][rs],
                                          acc2[mt][2][rs], acc2[mt][3][rs], c2s[mt][rs]);
                float2 f = h2tof2(hv);
                hfin[row][wid * 8 + t4 * 2]     = f.x;
                hfin[row][wid * 8 + t4 * 2 + 1] = f.y;
            }
    }
    __syncthreads();

    // ---- dense head ----
    if (tid < 32) {
        float s = bd[0];
        #pragma unroll
        for (int u = 0; u < 64; u++) s += hfin[tid][u] * Wd[u];
        out[b0 + tid] = fmaf(0.5f, tanhapx(0.5f * s), 0.5f);
    }
}

// ---------------------------------------------------------------------------
extern "C" void kernel_launch(void* const* d_in, const int* in_sizes, int n_in,
                              void* d_out, int out_size)
{
    const int*   tokens = (const int*)  d_in[0];
    const float* emb    = (const float*)d_in[1];
    const float* W1     = (const float*)d_in[2];
    const float* U1     = (const float*)d_in[3];
    const float* b1     = (const float*)d_in[4];
    const float* W2     = (const float*)d_in[5];
    const float* U2     = (const float*)d_in[6];
    const float* b2     = (const float*)d_in[7];
    const float* Wd     = (const float*)d_in[8];
    const float* bd     = (const float*)d_in[9];
    float* out = (float*)d_out;

    const int smem_gp = 2 * 128 * (112 + 8) * 2;   // 61440
    cudaFuncSetAttribute(gemm_P,     cudaFuncAttributeMaxDynamicSharedMemorySize, smem_gp);
    cudaFuncSetAttribute(lstm_both3, cudaFuncAttributeMaxDynamicSharedMemorySize, SM_TOTAL);

    conv_emb_kernel<<<10000 * 128 / 256, 256>>>(emb);
    conv_w1_kernel<<<256 * 128 / 256, 256>>>(W1);
    dim3 pgrid(2, 79);
    gemm_P<<<pgrid, 256, smem_gp>>>(b1);

    lstm_both3<<<BATCHN / 32, 256, SM_TOTAL>>>(tokens, U1, W2, U2, b2, Wd, bd, out);
}

// round 11
// speedup vs baseline: 1.5417x; 1.1132x over previous
#include <cuda_runtime.h>
#include <cuda_bf16.h>
#include <cuda_fp16.h>
#include <cstdint>

#define BATCHN 4096
#define SEQLEN 80
#define EMBD   100
#define UNITS  64
#define NG     256                 // 4*UNITS gates
#define PROWS  (79 * 128)          // vocab padded to m-tiles

// ---------------- device scratch (allocation-free: device globals) ----------
__device__ __nv_bfloat16 g_embbf[10000 * 128];           // emb->bf16, K padded to 128
__device__ __nv_bfloat16 g_Wt1  [256 * 128];             // W1^T bf16 [n][k], k padded
__device__ uint16_t      g_P    [(size_t)PROWS * 256];   // f16 table: emb@W1 + b1

// ---------------- helpers ---------------------------------------------------
__device__ __forceinline__ float tanhapx(float x) {
    float y; asm("tanh.approx.f32 %0, %1;" : "=f"(y) : "f"(x)); return y;
}
__device__ __forceinline__ uint32_t smem_u32(const void* p) {
    uint32_t a;
    asm("{ .reg .u64 t; cvta.to.shared.u64 t, %1; cvt.u32.u64 %0, t; }" : "=r"(a) : "l"(p));
    return a;
}
__device__ __forceinline__ uint32_t hmul2(uint32_t a, uint32_t b) {
    uint32_t d; asm("mul.rn.f16x2 %0,%1,%2;" : "=r"(d) : "r"(a), "r"(b)); return d;
}
__device__ __forceinline__ uint32_t hfma2(uint32_t a, uint32_t b, uint32_t c) {
    uint32_t d; asm("fma.rn.f16x2 %0,%1,%2,%3;" : "=r"(d) : "r"(a), "r"(b), "r"(c)); return d;
}
__device__ __forceinline__ uint32_t htanh2(uint32_t a) {
    uint32_t d; asm("tanh.approx.f16x2 %0,%1;" : "=r"(d) : "r"(a)); return d;
}
__device__ __forceinline__ uint32_t packh(float lo, float hi) {
    uint32_t d; asm("cvt.rn.f16x2.f32 %0,%1,%2;" : "=r"(d) : "f"(hi), "f"(lo)); return d;
}
__device__ __forceinline__ float2 h2tof2(uint32_t h) {
    float lo, hi;
    asm("{ .reg .b16 l,h; mov.b32 {l,h}, %2; cvt.f32.f16 %0, l; cvt.f32.f16 %1, h; }"
        : "=f"(lo), "=f"(hi) : "r"(h));
    return make_float2(lo, hi);
}
// bf16 HMMA, f32 acc (P-table GEMM only)
__device__ __forceinline__ void mma16816(float* d, const uint32_t* a, const uint32_t* b) {
    asm volatile(
        "mma.sync.aligned.m16n8k16.row.col.f32.bf16.bf16.f32 "
        "{%0,%1,%2,%3}, {%4,%5,%6,%7}, {%8,%9}, {%0,%1,%2,%3};"
        : "+f"(d[0]), "+f"(d[1]), "+f"(d[2]), "+f"(d[3])
        : "r"(a[0]), "r"(a[1]), "r"(a[2]), "r"(a[3]), "r"(b[0]), "r"(b[1]));
}
// f16 HMMA, f16 acc (scan)
__device__ __forceinline__ void mma16816hh(uint32_t* d, const uint32_t* a, const uint32_t* b) {
    asm volatile(
        "mma.sync.aligned.m16n8k16.row.col.f16.f16.f16.f16 "
        "{%0,%1}, {%2,%3,%4,%5}, {%6,%7}, {%0,%1};"
        : "+r"(d[0]), "+r"(d[1])
        : "r"(a[0]), "r"(a[1]), "r"(a[2]), "r"(a[3]), "r"(b[0]), "r"(b[1]));
}
__device__ __forceinline__ void ldmx4(uint32_t* r, uint32_t addr) {
    asm volatile("ldmatrix.sync.aligned.m8n8.x4.shared.b16 {%0,%1,%2,%3}, [%4];"
        : "=r"(r[0]), "=r"(r[1]), "=r"(r[2]), "=r"(r[3]) : "r"(addr));
}
__device__ __forceinline__ void cpa16(uint32_t dst, const void* gsrc) {
    asm volatile("{ .reg .u64 ga; cvta.to.global.u64 ga, %1; "
                 "cp.async.ca.shared.global [%0], [ga], 16; }"
                 :: "r"(dst), "l"(gsrc) : "memory");
}
#define CPA_COMMIT() asm volatile("cp.async.commit_group;" ::: "memory")
#define CPA_WAIT0()  asm volatile("cp.async.wait_group 0;" ::: "memory")
#define BAR512()     asm volatile("bar.sync 0, 512;" ::: "memory")

// f16x2 LSTM cell pair
__device__ __forceinline__ uint32_t lstm_cell2h(
    uint32_t zi, uint32_t zf, uint32_t zg, uint32_t zo, uint32_t& c2)
{
    const uint32_t H05 = 0x38003800u;   // (0.5, 0.5)
    uint32_t si = hfma2(htanh2(hmul2(zi, H05)), H05, H05);
    uint32_t sf = hfma2(htanh2(hmul2(zf, H05)), H05, H05);
    uint32_t tg = htanh2(zg);
    uint32_t so = hfma2(htanh2(hmul2(zo, H05)), H05, H05);
    c2 = hfma2(sf, c2, hmul2(si, tg));
    return hmul2(so, htanh2(c2));
}

// ---------------------------------------------------------------------------
// Pre-conversion kernels
// ---------------------------------------------------------------------------
__global__ void conv_emb_kernel(const float* __restrict__ emb) {
    int idx = blockIdx.x * 256 + threadIdx.x;
    int v = idx >> 7, c = idx & 127;
    g_embbf[idx] = (c < EMBD) ? __float2bfloat16(emb[v * EMBD + c]) : __nv_bfloat16(0.f);
}
__global__ void conv_w1_kernel(const float* __restrict__ W) {
    int idx = blockIdx.x * 256 + threadIdx.x;
    int n = idx >> 7, c = idx & 127;
    g_Wt1[idx] = (c < EMBD) ? __float2bfloat16(W[c * NG + n]) : __nv_bfloat16(0.f);
}

// ---------------------------------------------------------------------------
// P-table GEMM: P[v][0:256] = emb[v]@W1 + b1 (f16 out). Grid (2, 79).
// ---------------------------------------------------------------------------
__global__ void __launch_bounds__(256, 2) gemm_P(const float* __restrict__ bias)
{
    constexpr int K = 112, SA = K + 8, KH = K / 2;
    extern __shared__ __nv_bfloat16 smbf[];
    __nv_bfloat16* Asm = smbf;
    __nv_bfloat16* Bsm = smbf + 128 * SA;

    const int tid = threadIdx.x;
    const int m0  = blockIdx.y * 128;
    const int c0  = blockIdx.x * 128;

    for (int idx = tid; idx < 128 * KH; idx += 256) {
        int row = idx / KH, kc = (idx - row * KH) * 2;
        int m = m0 + row; if (m > 9999) m = 9999;
        *(uint32_t*)&Asm[row * SA + kc] = *(const uint32_t*)&g_embbf[(size_t)m * 128 + kc];
    }
    for (int idx = tid; idx < 128 * KH; idx += 256) {
        int row = idx / KH, kc = (idx - row * KH) * 2;
        *(uint32_t*)&Bsm[row * SA + kc] = *(const uint32_t*)&g_Wt1[(size_t)(c0 + row) * 128 + kc];
    }
    __syncthreads();

    const int wid  = tid >> 5, lid = tid & 31;
    const int wrow = wid & 3, wcol = wid >> 2;
    const int g    = lid >> 2, t = lid & 3;

    const uint32_t a_base = smem_u32(Asm);
    const uint32_t b_base = smem_u32(Bsm);
    const uint32_t a_lane = (uint32_t)((wrow * 32 + (lid & 15)) * SA * 2 + (lid >> 4) * 16);
    const uint32_t b_lane = (uint32_t)((wcol * 64 + (lid >> 4) * 8 + (lid & 7)) * SA * 2 +
                                       ((lid >> 3) & 1) * 16);

    float acc[2][8][4];
    #pragma unroll
    for (int mt = 0; mt < 2; mt++)
        #pragma unroll
        for (int nt = 0; nt < 8; nt++)
            #pragma unroll
            for (int r = 0; r < 4; r++) acc[mt][nt][r] = 0.f;

    #pragma unroll
    for (int s = 0; s < K / 16; s++) {
        uint32_t af[2][4], bfr[8][2];
        #pragma unroll
        for (int mt = 0; mt < 2; mt++)
            ldmx4(af[mt], a_base + a_lane + (uint32_t)(mt * 16 * SA * 2 + s * 32));
        #pragma unroll
        for (int np = 0; np < 4; np++) {
            uint32_t bq[4];
            ldmx4(bq, b_base + b_lane + (uint32_t)(np * 16 * SA * 2 + s * 32));
            bfr[np * 2][0] = bq[0]; bfr[np * 2][1] = bq[1];
            bfr[np * 2 + 1][0] = bq[2]; bfr[np * 2 + 1][1] = bq[3];
        }
        #pragma unroll
        for (int mt = 0; mt < 2; mt++)
            #pragma unroll
            for (int nt = 0; nt < 8; nt++)
                mma16816(acc[mt][nt], af[mt], bfr[nt]);
    }

    #pragma unroll
    for (int nt = 0; nt < 8; nt++) {
        const int col = c0 + wcol * 64 + nt * 8 + t * 2;
        float2 bb = *(const float2*)&bias[col];
        #pragma unroll
        for (int mt = 0; mt < 2; mt++) {
            const int row = m0 + wrow * 32 + mt * 16 + g;
            *(uint32_t*)&g_P[(size_t)row * 256 + col] =
                packh(acc[mt][nt][0] + bb.x, acc[mt][nt][1] + bb.y);
            *(uint32_t*)&g_P[(size_t)(row + 8) * 256 + col] =
                packh(acc[mt][nt][2] + bb.x, acc[mt][nt][3] + bb.y);
        }
    }
}

// ---------------------------------------------------------------------------
// Warp-specialized fused scan: 128 CTAs x 512 threads, 32 rows/CTA.
// Warps 0-7  (L1): z1 = P[token] + h1@U1          (bu1 only: 32 regs)
// Warps 8-15 (L2): z2 = b2 + h1@W2 + h2@U2, lag 1 (bw2+bu2: 64 regs)
// Two separate loops, lockstep via bar.sync 0,512 once per step.
// ---------------------------------------------------------------------------
#define XS_OFF  0                      // 2 x 32 x 528  = 33792 (f16 P rows)
#define H1_OFF  33792                  // 2 x 32 x 144  = 9216
#define H2_OFF  43008                  // 9216
#define TOK_OFF 52224                  // 32 x 80 x 2   = 5120
#define SM_TOTAL 57344

__global__ void __launch_bounds__(512, 1) lstm_ws(
    const int*   __restrict__ tokens,
    const float* __restrict__ U1,
    const float* __restrict__ W2,
    const float* __restrict__ U2,
    const float* __restrict__ b2,
    const float* __restrict__ Wd,
    const float* __restrict__ bd,
    float*       __restrict__ out)
{
    extern __shared__ char sm[];
    const int tid = threadIdx.x, wid = tid >> 5, lid = tid & 31;
    const int g = lid >> 2, t4 = lid & 3;
    const int w8 = wid & 7;
    const int b0 = blockIdx.x * 32;

    uint16_t* toks = (uint16_t*)(sm + TOK_OFF);

    {   // zero h buffers
        uint32_t* z1 = (uint32_t*)(sm + H1_OFF);
        for (int i = tid; i < 2 * 2 * 9216 / 4 / 2; i += 512) z1[i] = 0u;
    }
    for (int idx = tid; idx < 32 * SEQLEN; idx += 512)
        toks[idx] = (uint16_t)tokens[(size_t)(b0 + idx / SEQLEN) * SEQLEN + idx % SEQLEN];
    __syncthreads();

    const uint32_t xs_b = smem_u32(sm + XS_OFF);
    const uint32_t h1b0 = smem_u32(sm + H1_OFF), h1b1 = h1b0 + 4608;
    const uint32_t h2b0 = smem_u32(sm + H2_OFF), h2b1 = h2b0 + 4608;
    const uint32_t a_lane_h = (uint32_t)((lid & 15) * 144 + (lid >> 4) * 16);
    const int colb = (w8 * 8 + t4 * 2) * 2;

    if (wid < 8) {
        // =================== layer-1 group ===================
        auto stage_x = [&](int buf, int t) {
            const uint32_t dbase = xs_b + buf * 16896;
            #pragma unroll
            for (int i = 0; i < 4; i++) {
                int idx = tid + i * 256;       // 32 rows x 32 chunks of 16B
                int row = idx >> 5, ch = idx & 31;
                cpa16(dbase + row * 528 + ch * 16,
                      g_P + (size_t)toks[row * SEQLEN + t] * 256 + ch * 8);
            }
        };
        stage_x(0, 0);
        CPA_COMMIT();

        uint32_t bu1[4][4][2];
        #pragma unroll
        for (int gg = 0; gg < 4; gg++) {
            const int n = gg * 64 + w8 * 8 + g;
            #pragma unroll
            for (int kt = 0; kt < 4; kt++) {
                const int k0 = kt * 16 + t4 * 2;
                bu1[gg][kt][0] = packh(U1[(size_t)k0 * NG + n],       U1[(size_t)(k0 + 1) * NG + n]);
                bu1[gg][kt][1] = packh(U1[(size_t)(k0 + 8) * NG + n], U1[(size_t)(k0 + 9) * NG + n]);
            }
        }
        CPA_WAIT0();
        BAR512();                                   // bar0: x(0)+weights ready

        uint32_t c1[2][2] = {{0u, 0u}, {0u, 0u}};

        // ---- t = 0 peel: h1(0) = cell(x(0)); stage x(1) ----
        stage_x(1, 1);
        CPA_COMMIT();
        {
            const char* xb = sm + XS_OFF;
            char* h1wr = sm + H1_OFF + 4608;        // buf1
            #pragma unroll
            for (int mt = 0; mt < 2; mt++)
                #pragma unroll
                for (int rs = 0; rs < 2; rs++) {
                    const int row = mt * 16 + g + rs * 8;
                    uint32_t z0 = *(const uint32_t*)(xb + row * 528 + 0 * 128 + colb);
                    uint32_t z1v = *(const uint32_t*)(xb + row * 528 + 1 * 128 + colb);
                    uint32_t z2 = *(const uint32_t*)(xb + row * 528 + 2 * 128 + colb);
                    uint32_t z3 = *(const uint32_t*)(xb + row * 528 + 3 * 128 + colb);
                    uint32_t hv = lstm_cell2h(z0, z1v, z2, z3, c1[mt][rs]);
                    *(uint32_t*)(h1wr + row * 144 + colb) = hv;
                }
        }
        CPA_WAIT0();
        BAR512();                                   // bar1

        for (int t = 1; t < SEQLEN; ++t) {
            if (t + 1 < SEQLEN) stage_x((t + 1) & 1, t + 1);
            CPA_COMMIT();

            const uint32_t h1rd = (t & 1) ? h1b1 : h1b0;
            uint32_t acc1[2][4][2];
            const char* xb = sm + XS_OFF + (t & 1) * 16896;
            #pragma unroll
            for (int mt = 0; mt < 2; mt++)
                #pragma unroll
                for (int gg = 0; gg < 4; gg++) {
                    acc1[mt][gg][0] = *(const uint32_t*)(xb + (mt * 16 + g) * 528 + gg * 128 + colb);
                    acc1[mt][gg][1] = *(const uint32_t*)(xb + (mt * 16 + g + 8) * 528 + gg * 128 + colb);
                }
            #pragma unroll
            for (int kt = 0; kt < 4; kt++) {
                uint32_t a0[4], a1[4];
                ldmx4(a0, h1rd + a_lane_h + (uint32_t)(kt * 32));
                ldmx4(a1, h1rd + a_lane_h + (uint32_t)(16 * 144 + kt * 32));
                #pragma unroll
                for (int gg = 0; gg < 4; gg++) {
                    mma16816hh(acc1[0][gg], a0, bu1[gg][kt]);
                    mma16816hh(acc1[1][gg], a1, bu1[gg][kt]);
                }
            }
            char* h1wr = sm + H1_OFF + ((t & 1) ^ 1) * 4608;
            #pragma unroll
            for (int mt = 0; mt < 2; mt++)
                #pragma unroll
                for (int rs = 0; rs < 2; rs++) {
                    const int row = mt * 16 + g + rs * 8;
                    uint32_t hv = lstm_cell2h(acc1[mt][0][rs], acc1[mt][1][rs],
                                              acc1[mt][2][rs], acc1[mt][3][rs], c1[mt][rs]);
                    *(uint32_t*)(h1wr + row * 144 + colb) = hv;
                }
            CPA_WAIT0();
            BAR512();                               // bar2..80
        }
        BAR512();                                   // bar81 (final)
    } else {
        // =================== layer-2 group ===================
        uint32_t bw2[4][4][2], bu2[4][4][2], rb2[4];
        #pragma unroll
        for (int gg = 0; gg < 4; gg++) {
            const int n = gg * 64 + w8 * 8 + g;
            #pragma unroll
            for (int kt = 0; kt < 4; kt++) {
                const int k0 = kt * 16 + t4 * 2;
                bw2[gg][kt][0] = packh(W2[(size_t)k0 * NG + n],       W2[(size_t)(k0 + 1) * NG + n]);
                bw2[gg][kt][1] = packh(W2[(size_t)(k0 + 8) * NG + n], W2[(size_t)(k0 + 9) * NG + n]);
                bu2[gg][kt][0] = packh(U2[(size_t)k0 * NG + n],       U2[(size_t)(k0 + 1) * NG + n]);
                bu2[gg][kt][1] = packh(U2[(size_t)(k0 + 8) * NG + n], U2[(size_t)(k0 + 9) * NG + n]);
            }
            const int col = gg * 64 + w8 * 8 + t4 * 2;
            rb2[gg] = packh(b2[col], b2[col + 1]);
        }
        BAR512();                                   // bar0
        BAR512();                                   // bar1 (warm-up; h1(0) ready after)

        uint32_t c2s[2][2] = {{0u, 0u}, {0u, 0u}};

        for (int t = 1; t < SEQLEN; ++t) {
            const uint32_t h1rd = (t & 1) ? h1b1 : h1b0;
            const uint32_t h2rd = (t & 1) ? h2b1 : h2b0;
            uint32_t acc2[2][4][2];
            #pragma unroll
            for (int mt = 0; mt < 2; mt++)
                #pragma unroll
                for (int gg = 0; gg < 4; gg++) { acc2[mt][gg][0] = rb2[gg]; acc2[mt][gg][1] = rb2[gg]; }
            #pragma unroll
            for (int kt = 0; kt < 4; kt++) {
                uint32_t a0[4], a1[4];
                ldmx4(a0, h1rd + a_lane_h + (uint32_t)(kt * 32));
                ldmx4(a1, h1rd + a_lane_h + (uint32_t)(16 * 144 + kt * 32));
                #pragma unroll
                for (int gg = 0; gg < 4; gg++) {
                    mma16816hh(acc2[0][gg], a0, bw2[gg][kt]);
                    mma16816hh(acc2[1][gg], a1, bw2[gg][kt]);
                }
            }
            #pragma unroll
            for (int kt = 0; kt < 4; kt++) {
                uint32_t a0[4], a1[4];
                ldmx4(a0, h2rd + a_lane_h + (uint32_t)(kt * 32));
                ldmx4(a1, h2rd + a_lane_h + (uint32_t)(16 * 144 + kt * 32));
                #pragma unroll
                for (int gg = 0; gg < 4; gg++) {
                    mma16816hh(acc2[0][gg], a0, bu2[gg][kt]);
                    mma16816hh(acc2[1][gg], a1, bu2[gg][kt]);
                }
            }
            char* h2wr = sm + H2_OFF + ((t & 1) ^ 1) * 4608;
            #pragma unroll
            for (int mt = 0; mt < 2; mt++)
                #pragma unroll
                for (int rs = 0; rs < 2; rs++) {
                    const int row = mt * 16 + g + rs * 8;
                    uint32_t hv = lstm_cell2h(acc2[mt][0][rs], acc2[mt][1][rs],
                                              acc2[mt][2][rs], acc2[mt][3][rs], c2s[mt][rs]);
                    *(uint32_t*)(h2wr + row * 144 + colb) = hv;
                }
            BAR512();                               // bar2..80
        }

        // ---- t = 80 epilogue: h2(79) -> hfin (aliases xs; L1 xs reads done) ----
        {
            uint32_t acc2[2][4][2];
            #pragma unroll
            for (int mt = 0; mt < 2; mt++)
                #pragma unroll
                for (int gg = 0; gg < 4; gg++) { acc2[mt][gg][0] = rb2[gg]; acc2[mt][gg][1] = rb2[gg]; }
            #pragma unroll
            for (int kt = 0; kt < 4; kt++) {
                uint32_t a0[4], a1[4];
                ldmx4(a0, h1b0 + a_lane_h + (uint32_t)(kt * 32));
                ldmx4(a1, h1b0 + a_lane_h + (uint32_t)(16 * 144 + kt * 32));
                #pragma unroll
                for (int gg = 0; gg < 4; gg++) {
                    mma16816hh(acc2[0][gg], a0, bw2[gg][kt]);
                    mma16816hh(acc2[1][gg], a1, bw2[gg][kt]);
                }
            }
            #pragma unroll
            for (int kt = 0; kt < 4; kt++) {
                uint32_t a0[4], a1[4];
                ldmx4(a0, h2b0 + a_lane_h + (uint32_t)(kt * 32));
                ldmx4(a1, h2b0 + a_lane_h + (uint32_t)(16 * 144 + kt * 32));
                #pragma unroll
                for (int gg = 0; gg < 4; gg++) {
                    mma16816hh(acc2[0][gg], a0, bu2[gg][kt]);
                    mma16816hh(acc2[1][gg], a1, bu2[gg][kt]);
                }
            }
            float (*hfin)[68] = reinterpret_cast<float(*)[68]>(sm + XS_OFF);
            #pragma unroll
            for (int mt = 0; mt < 2; mt++)
                #pragma unroll
                for (int rs = 0; rs < 2; rs++) {
                    const int row = mt * 16 + g + rs * 8;
                    uint32_t hv = lstm_cell2h(acc2[mt][0][rs], acc2[mt][1][rs],
                                              acc2[mt][2][rs], acc2[mt][3][rs], c2s[mt][rs]);
                    float2 f = h2tof2(hv);
                    hfin[row][w8 * 8 + t4 * 2]     = f.x;
                    hfin[row][w8 * 8 + t4 * 2 + 1] = f.y;
                }
        }
        BAR512();                                   // bar81 (final)
    }

    // -------------------- dense head --------------------
    if (tid < 32) {
        float (*hfin)[68] = reinterpret_cast<float(*)[68]>(sm + XS_OFF);
        float s = bd[0];
        #pragma unroll
        for (int u = 0; u < 64; u++) s += hfin[tid][u] * Wd[u];
        out[b0 + tid] = fmaf(0.5f, tanhapx(0.5f * s), 0.5f);
    }
}

// ---------------------------------------------------------------------------
extern "C" void kernel_launch(void* const* d_in, const int* in_sizes, int n_in,
                              void* d_out, int out_size)
{
    const int*   tokens = (const int*)  d_in[0];
    const float* emb    = (const float*)d_in[1];
    const float* W1     = (const float*)d_in[2];
    const float* U1     = (const float*)d_in[3];
    const float* b1     = (const float*)d_in[4];
    const float* W2     = (const float*)d_in[5];
    const float* U2     = (const float*)d_in[6];
    const float* b2     = (const float*)d_in[7];
    const float* Wd     = (const float*)d_in[8];
    const float* bd     = (const float*)d_in[9];
    float* out = (float*)d_out;

    const int smem_gp = 2 * 128 * (112 + 8) * 2;   // 61440
    cudaFuncSetAttribute(gemm_P,  cudaFuncAttributeMaxDynamicSharedMemorySize, smem_gp);
    cudaFuncSetAttribute(lstm_ws, cudaFuncAttributeMaxDynamicSharedMemorySize, SM_TOTAL);

    conv_emb_kernel<<<10000 * 128 / 256, 256>>>(emb);
    conv_w1_kernel<<<256 * 128 / 256, 256>>>(W1);
    dim3 pgrid(2, 79);
    gemm_P<<<pgrid, 256, smem_gp>>>(b1);

    lstm_ws<<<BATCHN / 32, 512, SM_TOTAL>>>(tokens, U1, W2, U2, b2, Wd, bd, out);
}